// round 2
// baseline (speedup 1.0000x reference)
#include <cuda_runtime.h>
#include <cuda_bf16.h>

// ---------------------------------------------------------------------------
// DependencyParseModel: 2-layer BiLSTM (SEQ=512, H=128) -> pairwise tanh MLP
// scorer (512^3) -> column normalize -> row softmax.
//
// Round 2: same fp32-exact baseline as R1, but kernel_launch is now PURE
// kernel launches (no cudaGetSymbolAddress) — all scratch buffers are
// selected device-side by integer id.
// ---------------------------------------------------------------------------

#define SEQ 512
#define H   128
#define G4  512      // 4*H gates
#define D2  256      // 2*H concat

// ---- device scratch (no allocations allowed) ----
__device__ float g_x[SEQ * H];            // embedded input [512][128]
__device__ float g_pre[2][SEQ * G4];      // per-direction pre-activations
__device__ float g_WT[4][H * G4];         // transposed Whh (l0f,l0b,l1f,l1b)
__device__ float g_h0out[SEQ * D2];       // layer0 output concat [512][256]
__device__ float g_h1out[SEQ * D2];       // layer1 output concat [512][256]
__device__ float g_A[SEQ * 512];          // h@W1a.T + b1
__device__ float g_B[SEQ * 512];          // h@W1b.T
__device__ float g_scores[SEQ * SEQ];
__device__ float g_colsum[SEQ];

// buffer ids for device-side selection
#define BUF_X     0
#define BUF_PREF  1
#define BUF_PREB  2
#define BUF_H0OUT 3
#define BUF_H1OUT 4
#define BUF_A     5
#define BUF_B     6

__device__ __forceinline__ float* selbuf(int s) {
    switch (s) {
        case BUF_X:     return g_x;
        case BUF_PREF:  return g_pre[0];
        case BUF_PREB:  return g_pre[1];
        case BUF_H0OUT: return g_h0out;
        case BUF_H1OUT: return g_h1out;
        case BUF_A:     return g_A;
        default:        return g_B;
    }
}

// ---- math helpers (accurate: ~1e-6, well inside 1e-3 tolerance) ----
__device__ __forceinline__ float sigmoid_(float x) {
    float e = __expf(-x);
    return __fdividef(1.0f, 1.0f + e);
}
__device__ __forceinline__ float tanh_(float x) {
    float ax = fabsf(x);
    float e  = __expf(-2.0f * ax);                 // in (0,1]
    float r  = __fdividef(1.0f - e, 1.0f + e);     // tanh(|x|)
    return __int_as_float(__float_as_int(r) | (__float_as_int(x) & 0x80000000));
}

// ---------------------------------------------------------------------------
// 1) embedding gather: x[t] = [word_emb[wid[t]] (100) | tag_emb[tid[t]] (28)]
// ---------------------------------------------------------------------------
__global__ void k_embed(const int* __restrict__ wid, const int* __restrict__ tid,
                        const float* __restrict__ wemb, const float* __restrict__ temb) {
    int t = blockIdx.x, k = threadIdx.x;   // <<<512,128>>>
    float v;
    if (k < 100) v = wemb[wid[t] * 100 + k];
    else         v = temb[tid[t] * 28 + (k - 100)];
    g_x[t * H + k] = v;
}

// ---------------------------------------------------------------------------
// 2) transpose the four Whh matrices: WT[k*512 + j] = Whh[j*128 + k]
// ---------------------------------------------------------------------------
__global__ void k_trans(const float* __restrict__ w0, const float* __restrict__ w1,
                        const float* __restrict__ w2, const float* __restrict__ w3) {
    int mtx = blockIdx.y;                  // grid (256,4), block 256
    const float* W = (mtx == 0) ? w0 : (mtx == 1) ? w1 : (mtx == 2) ? w2 : w3;
    int idx = blockIdx.x * blockDim.x + threadIdx.x;  // 0..65535
    int j = idx >> 7, k = idx & 127;
    g_WT[mtx][k * G4 + j] = W[idx];
}

// ---------------------------------------------------------------------------
// 3) generic GEMM: C[512][512] = X[512][K] @ W'[512][K]^T (+ b1 + b2)
//    X = selbuf(srcSel) with leading dim ldx; C = selbuf(dstSel), ld 512.
//    W row r lives at W[r*ldw + woff + k].
// ---------------------------------------------------------------------------
__global__ void k_gemm(int srcSel, int ldx,
                       const float* __restrict__ W, int ldw, int woff,
                       const float* __restrict__ b1, const float* __restrict__ b2,
                       int dstSel, int K) {
    const float* X = selbuf(srcSel);
    float*       C = selbuf(dstSel);
    __shared__ float Xs[32][33];
    __shared__ float Ws[32][33];
    int tx = threadIdx.x, ty = threadIdx.y;           // block (32,32)
    int row = blockIdx.y * 32 + ty;
    int col = blockIdx.x * 32 + tx;
    float acc = 0.0f;
    for (int k0 = 0; k0 < K; k0 += 32) {
        Xs[ty][tx] = X[row * ldx + k0 + tx];
        Ws[ty][tx] = W[(blockIdx.x * 32 + ty) * ldw + woff + k0 + tx];
        __syncthreads();
#pragma unroll
        for (int kk = 0; kk < 32; kk++)
            acc += Xs[ty][kk] * Ws[tx][kk];
        __syncthreads();
    }
    float b = 0.0f;
    if (b1) b += b1[col];
    if (b2) b += b2[col];
    C[row * 512 + col] = acc + b;
}

// ---------------------------------------------------------------------------
// 4) LSTM recurrence, one CTA (128 threads) per direction.
//    Thread t computes gate rows 4t..4t+3 via float4 weight loads from L2,
//    then the per-unit (i,f,g,o) update for hidden unit t.
// ---------------------------------------------------------------------------
__global__ void __launch_bounds__(128)
k_recur(int layer, const float* __restrict__ h0, const float* __restrict__ c0) {
    int d = blockIdx.x;                 // 0 = forward, 1 = backward
    int t = threadIdx.x;                // 0..127
    const float*  pre = g_pre[d];
    const float4* WT4 = (const float4*)(g_WT[layer * 2 + d]);
    float* out = layer ? g_h1out : g_h0out;

    __shared__ float  h_s[H];
    __shared__ float4 g_s4[H];
    float* g_s = (float*)g_s4;

    int row0 = (2 * layer + d) * H;
    h_s[t] = h0[row0 + t];
    float c = c0[row0 + t];
    __syncthreads();

    for (int s = 0; s < SEQ; s++) {
        int ti = d ? (SEQ - 1 - s) : s;
        const float4* pr = (const float4*)(pre + (size_t)ti * G4);
        float4 acc = pr[t];
#pragma unroll 8
        for (int k = 0; k < H; k++) {
            float hk = h_s[k];
            float4 w = WT4[k * H + t];   // rows 4t..4t+3, coalesced
            acc.x += w.x * hk;
            acc.y += w.y * hk;
            acc.z += w.z * hk;
            acc.w += w.w * hk;
        }
        g_s4[t] = acc;                   // gates rows 4t..4t+3
        __syncthreads();

        float i_ = sigmoid_(g_s[t]);
        float f_ = sigmoid_(g_s[H + t]);
        float gg = tanh_(g_s[2 * H + t]);
        float o_ = sigmoid_(g_s[3 * H + t]);
        c = f_ * c + i_ * gg;
        float h = o_ * tanh_(c);
        h_s[t] = h;
        out[ti * D2 + d * H + t] = h;
        __syncthreads();
    }
}

// ---------------------------------------------------------------------------
// 5) pairwise scorer: scores[n][m] = sum_h tanh(A[n][h]+B[m][h]) * W2[h] + b2
//    (b1 already folded into A). Diagonal zeroed.
// ---------------------------------------------------------------------------
__global__ void k_pairwise(const float* __restrict__ W2, const float* __restrict__ b2) {
    __shared__ float As[32][33];
    __shared__ float Bs[32][33];
    __shared__ float w2s[32];
    int tx = threadIdx.x, ty = threadIdx.y;     // block (32,32)
    int n = blockIdx.y * 32 + ty;
    int m = blockIdx.x * 32 + tx;
    float acc = 0.0f;
    for (int h0 = 0; h0 < 512; h0 += 32) {
        As[ty][tx] = g_A[n * 512 + h0 + tx];
        Bs[ty][tx] = g_B[(blockIdx.x * 32 + ty) * 512 + h0 + tx];
        if (ty == 0) w2s[tx] = W2[h0 + tx];
        __syncthreads();
#pragma unroll
        for (int hh = 0; hh < 32; hh++) {
            float v = As[ty][hh] + Bs[tx][hh];
            acc += tanh_(v) * w2s[hh];
        }
        __syncthreads();
    }
    float val = acc + b2[0];
    if (n == m) val = 0.0f;
    g_scores[n * 512 + m] = val;
}

// ---------------------------------------------------------------------------
// 6) column sums (axis 0)
// ---------------------------------------------------------------------------
__global__ void k_colsum() {
    int m = blockIdx.x * blockDim.x + threadIdx.x;   // <<<4,128>>>
    float s = 0.0f;
    for (int n = 0; n < SEQ; n++)
        s += g_scores[n * 512 + m];
    g_colsum[m] = s;
}

// ---------------------------------------------------------------------------
// 7) divide by colsum, then row softmax (axis 1)
// ---------------------------------------------------------------------------
__global__ void k_softmax(float* __restrict__ out) {
    __shared__ float red[512];
    int n = blockIdx.x, m = threadIdx.x;  // <<<512,512>>>
    float v = g_scores[n * 512 + m] / g_colsum[m];

    red[m] = v;
    __syncthreads();
    for (int off = 256; off > 0; off >>= 1) {
        if (m < off) red[m] = fmaxf(red[m], red[m + off]);
        __syncthreads();
    }
    float mx = red[0];
    __syncthreads();

    float p = __expf(v - mx);
    red[m] = p;
    __syncthreads();
    for (int off = 256; off > 0; off >>= 1) {
        if (m < off) red[m] = red[m] + red[m + off];
        __syncthreads();
    }
    float sum = red[0];
    out[n * 512 + m] = p / sum;
}

// ---------------------------------------------------------------------------
// launch — ONLY kernel launches, nothing else.
// ---------------------------------------------------------------------------
extern "C" void kernel_launch(void* const* d_in, const int* in_sizes, int n_in,
                              void* d_out, int out_size) {
    const int*   word_ids = (const int*)d_in[0];
    const int*   tag_ids  = (const int*)d_in[1];
    const float* wemb     = (const float*)d_in[2];
    const float* temb     = (const float*)d_in[3];
    const float* h0       = (const float*)d_in[4];
    const float* c0       = (const float*)d_in[5];
    const float* Wih_l0f  = (const float*)d_in[6];
    const float* Whh_l0f  = (const float*)d_in[7];
    const float* bih_l0f  = (const float*)d_in[8];
    const float* bhh_l0f  = (const float*)d_in[9];
    const float* Wih_l0b  = (const float*)d_in[10];
    const float* Whh_l0b  = (const float*)d_in[11];
    const float* bih_l0b  = (const float*)d_in[12];
    const float* bhh_l0b  = (const float*)d_in[13];
    const float* Wih_l1f  = (const float*)d_in[14];
    const float* Whh_l1f  = (const float*)d_in[15];
    const float* bih_l1f  = (const float*)d_in[16];
    const float* bhh_l1f  = (const float*)d_in[17];
    const float* Wih_l1b  = (const float*)d_in[18];
    const float* Whh_l1b  = (const float*)d_in[19];
    const float* bih_l1b  = (const float*)d_in[20];
    const float* bhh_l1b  = (const float*)d_in[21];
    const float* W1       = (const float*)d_in[22];
    const float* b1       = (const float*)d_in[23];
    const float* W2       = (const float*)d_in[24];
    const float* b2       = (const float*)d_in[25];
    float* out = (float*)d_out;

    dim3 gblk(32, 32), ggrd(16, 16);
    const float* nul = (const float*)0;

    // embeddings + weight transposes
    k_embed<<<512, 128>>>(word_ids, tag_ids, wemb, temb);
    k_trans<<<dim3(256, 4), 256>>>(Whh_l0f, Whh_l0b, Whh_l1f, Whh_l1b);

    // layer 0: pre-activations + recurrence
    k_gemm<<<ggrd, gblk>>>(BUF_X, H, Wih_l0f, H, 0, bih_l0f, bhh_l0f, BUF_PREF, H);
    k_gemm<<<ggrd, gblk>>>(BUF_X, H, Wih_l0b, H, 0, bih_l0b, bhh_l0b, BUF_PREB, H);
    k_recur<<<2, 128>>>(0, h0, c0);

    // layer 1: pre-activations + recurrence
    k_gemm<<<ggrd, gblk>>>(BUF_H0OUT, D2, Wih_l1f, D2, 0, bih_l1f, bhh_l1f, BUF_PREF, D2);
    k_gemm<<<ggrd, gblk>>>(BUF_H0OUT, D2, Wih_l1b, D2, 0, bih_l1b, bhh_l1b, BUF_PREB, D2);
    k_recur<<<2, 128>>>(1, h0, c0);

    // MLP projections: A = h@W1[:, :256].T + b1 ; B = h@W1[:, 256:].T
    k_gemm<<<ggrd, gblk>>>(BUF_H1OUT, D2, W1, 512, 0,   b1,  nul, BUF_A, D2);
    k_gemm<<<ggrd, gblk>>>(BUF_H1OUT, D2, W1, 512, 256, nul, nul, BUF_B, D2);

    // pairwise scores, normalize, softmax
    k_pairwise<<<ggrd, gblk>>>(W2, b2);
    k_colsum<<<4, 128>>>();
    k_softmax<<<512, 512>>>(out);
}

// round 3
// speedup vs baseline: 4.4753x; 4.4753x over previous
#include <cuda_runtime.h>
#include <cuda_bf16.h>
#include <cstdint>

// ---------------------------------------------------------------------------
// DependencyParseModel: 2-layer BiLSTM (SEQ=512, H=128) -> pairwise tanh MLP
// scorer (512^3) -> column normalize -> row softmax.
//
// Round 3: recurrence rebuilt as a 4-CTA-cluster kernel per direction.
//   - Whh lives in REGISTERS (128 fp32/thread, 64KB/CTA) -> zero weight
//     traffic in the 512-step serial loop (was L2-latency-bound streaming).
//   - units partitioned across CTAs (32 each); h exchanged via DSMEM
//     (st.shared::cluster) + one cluster mbarrier per step.
// ---------------------------------------------------------------------------

#define SEQ 512
#define H   128
#define G4  512      // 4*H gates
#define D2  256      // 2*H concat

// ---- device scratch (no allocations allowed) ----
__device__ float g_x[SEQ * H];            // embedded input [512][128]
__device__ float g_pre[2][SEQ * G4];      // per-direction pre-activations
__device__ float g_h0out[SEQ * D2];       // layer0 output concat [512][256]
__device__ float g_h1out[SEQ * D2];       // layer1 output concat [512][256]
__device__ float g_A[SEQ * 512];          // h@W1a.T + b1
__device__ float g_B[SEQ * 512];          // h@W1b.T
__device__ float g_scores[SEQ * SEQ];
__device__ float g_colsum[SEQ];

// buffer ids for device-side selection
#define BUF_X     0
#define BUF_PREF  1
#define BUF_PREB  2
#define BUF_H0OUT 3
#define BUF_H1OUT 4
#define BUF_A     5
#define BUF_B     6

__device__ __forceinline__ float* selbuf(int s) {
    switch (s) {
        case BUF_X:     return g_x;
        case BUF_PREF:  return g_pre[0];
        case BUF_PREB:  return g_pre[1];
        case BUF_H0OUT: return g_h0out;
        case BUF_H1OUT: return g_h1out;
        case BUF_A:     return g_A;
        default:        return g_B;
    }
}

// ---- math helpers (accurate: ~1e-6) ----
__device__ __forceinline__ float sigmoid_(float x) {
    float e = __expf(-x);
    return __fdividef(1.0f, 1.0f + e);
}
__device__ __forceinline__ float tanh_(float x) {
    float ax = fabsf(x);
    float e  = __expf(-2.0f * ax);                 // in (0,1]
    float r  = __fdividef(1.0f - e, 1.0f + e);     // tanh(|x|)
    return __int_as_float(__float_as_int(r) | (__float_as_int(x) & 0x80000000));
}

// ---- cluster / mbarrier helpers ----
__device__ __forceinline__ uint32_t s2u_(const void* p) {
    uint32_t a;
    asm("{ .reg .u64 t; cvta.to.shared.u64 t, %1; cvt.u32.u64 %0, t; }"
        : "=r"(a) : "l"(p));
    return a;
}
__device__ __forceinline__ uint32_t mapa_(uint32_t a, uint32_t rank) {
    uint32_t o;
    asm("mapa.shared::cluster.u32 %0, %1, %2;" : "=r"(o) : "r"(a), "r"(rank));
    return o;
}
__device__ __forceinline__ void st_remote_f32(uint32_t a, float v) {
    asm volatile("st.shared::cluster.f32 [%0], %1;" :: "r"(a), "f"(v) : "memory");
}
__device__ __forceinline__ void mbar_init_(uint32_t a, uint32_t cnt) {
    asm volatile("mbarrier.init.shared.b64 [%0], %1;" :: "r"(a), "r"(cnt) : "memory");
}
__device__ __forceinline__ void mbar_arrive_cluster(uint32_t a) {
    asm volatile("mbarrier.arrive.release.cluster.shared::cluster.b64 _, [%0];"
                 :: "r"(a) : "memory");
}
__device__ __forceinline__ void mbar_wait_(uint32_t a, uint32_t par) {
    asm volatile(
        "{\n\t.reg .pred P;\n\t"
        "WL_%=:\n\t"
        "mbarrier.try_wait.parity.acquire.cluster.shared::cta.b64 P, [%0], %1;\n\t"
        "@!P bra WL_%=;\n\t}"
        :: "r"(a), "r"(par) : "memory");
}

// ---------------------------------------------------------------------------
// 1) embedding gather
// ---------------------------------------------------------------------------
__global__ void k_embed(const int* __restrict__ wid, const int* __restrict__ tid,
                        const float* __restrict__ wemb, const float* __restrict__ temb) {
    int t = blockIdx.x, k = threadIdx.x;   // <<<512,128>>>
    float v;
    if (k < 100) v = wemb[wid[t] * 100 + k];
    else         v = temb[tid[t] * 28 + (k - 100)];
    g_x[t * H + k] = v;
}

// ---------------------------------------------------------------------------
// 2) generic GEMM: C[512][512] = X[512][K] @ W'[512][K]^T (+ b1 + b2)
// ---------------------------------------------------------------------------
__global__ void k_gemm(int srcSel, int ldx,
                       const float* __restrict__ W, int ldw, int woff,
                       const float* __restrict__ b1, const float* __restrict__ b2,
                       int dstSel, int K) {
    const float* X = selbuf(srcSel);
    float*       C = selbuf(dstSel);
    __shared__ float Xs[32][33];
    __shared__ float Ws[32][33];
    int tx = threadIdx.x, ty = threadIdx.y;           // block (32,32)
    int row = blockIdx.y * 32 + ty;
    int col = blockIdx.x * 32 + tx;
    float acc = 0.0f;
    for (int k0 = 0; k0 < K; k0 += 32) {
        Xs[ty][tx] = X[row * ldx + k0 + tx];
        Ws[ty][tx] = W[(blockIdx.x * 32 + ty) * ldw + woff + k0 + tx];
        __syncthreads();
#pragma unroll
        for (int kk = 0; kk < 32; kk++)
            acc += Xs[ty][kk] * Ws[tx][kk];
        __syncthreads();
    }
    float b = 0.0f;
    if (b1) b += b1[col];
    if (b2) b += b2[col];
    C[row * 512 + col] = acc + b;
}

// ---------------------------------------------------------------------------
// 3) LSTM recurrence: grid 8, cluster 4. CTAs 0-3 = forward, 4-7 = backward.
//    Cluster rank r owns hidden units [32r, 32r+32). Thread t (gate=t>>5,
//    ul=t&31) computes global gate row R = gate*128 + 32r + ul, with the
//    weight row held in 128 registers.
// ---------------------------------------------------------------------------
__global__ void __launch_bounds__(128, 1) __cluster_dims__(4, 1, 1)
k_recur(int layer, const float* __restrict__ Whh_f, const float* __restrict__ Whh_b,
        const float* __restrict__ h0, const float* __restrict__ c0) {
    const int d = blockIdx.x >> 2;          // 0 = forward, 1 = backward
    const int r = blockIdx.x & 3;           // cluster rank
    const int t = threadIdx.x;              // 0..127
    const int gate = t >> 5, ul = t & 31;
    const int R = gate * 128 + r * 32 + ul; // global gate row

    const float* __restrict__ Whh = d ? Whh_b : Whh_f;
    const float* __restrict__ pre = g_pre[d];
    float* __restrict__ out = layer ? g_h1out : g_h0out;

    __shared__ float h_s[2][H];
    __shared__ float gb[H];
    __shared__ __align__(8) unsigned long long mbar;

    const uint32_t mb_a = s2u_(&mbar);
    if (t == 0) mbar_init_(mb_a, 4);

    // preload weight row into registers (one-time, outside the serial loop)
    float w[H];
    {
        const float4* Wr = (const float4*)(Whh + (size_t)R * H);
#pragma unroll
        for (int k4 = 0; k4 < 32; k4++) {
            float4 v = Wr[k4];
            w[4 * k4 + 0] = v.x; w[4 * k4 + 1] = v.y;
            w[4 * k4 + 2] = v.z; w[4 * k4 + 3] = v.w;
        }
    }

    // init state
    const int row0 = (2 * layer + d) * H;
    h_s[0][t] = h0[row0 + t];
    float c = (t < 32) ? c0[row0 + r * 32 + t] : 0.0f;

    // mbar init + h_s visible cluster-wide before first remote ops
    asm volatile("barrier.cluster.arrive.aligned;" ::: "memory");
    asm volatile("barrier.cluster.wait.aligned;" ::: "memory");

    for (int s = 0; s < SEQ; s++) {
        const int ti = d ? (SEQ - 1 - s) : s;
        const float pv = pre[(size_t)ti * G4 + R];   // LDG, hidden under FFMAs

        const float4* h4 = (const float4*)h_s[s & 1];
        float acc = 0.0f;
#pragma unroll
        for (int k4 = 0; k4 < 32; k4++) {
            float4 hv = h4[k4];                       // broadcast LDS
            acc += w[4 * k4 + 0] * hv.x;
            acc += w[4 * k4 + 1] * hv.y;
            acc += w[4 * k4 + 2] * hv.z;
            acc += w[4 * k4 + 3] * hv.w;
        }
        gb[t] = acc + pv;
        __syncthreads();

        if (t < 32) {
            float i_ = sigmoid_(gb[t]);
            float f_ = sigmoid_(gb[32 + t]);
            float gg = tanh_(gb[64 + t]);
            float o_ = sigmoid_(gb[96 + t]);
            c = f_ * c + i_ * gg;
            float h = o_ * tanh_(c);

            const int u = r * 32 + t;
            h_s[(s + 1) & 1][u] = h;                  // local
            uint32_t la = s2u_(&h_s[(s + 1) & 1][u]);
#pragma unroll
            for (int p = 0; p < 4; p++) {
                if (p != r) st_remote_f32(mapa_(la, (uint32_t)p), h);
            }
            out[(size_t)ti * D2 + d * H + u] = h;     // final output
        }
        __syncthreads();                              // order stores before arrive
        if (t == 0) {
#pragma unroll
            for (int p = 0; p < 4; p++)
                mbar_arrive_cluster(mapa_(mb_a, (uint32_t)p));
        }
        mbar_wait_(mb_a, s & 1);
    }
}

// ---------------------------------------------------------------------------
// 4) pairwise scorer: scores[n][m] = sum_h tanh(A[n][h]+B[m][h]) * W2[h] + b2
// ---------------------------------------------------------------------------
__global__ void k_pairwise(const float* __restrict__ W2, const float* __restrict__ b2) {
    __shared__ float As[32][33];
    __shared__ float Bs[32][33];
    __shared__ float w2s[32];
    int tx = threadIdx.x, ty = threadIdx.y;     // block (32,32)
    int n = blockIdx.y * 32 + ty;
    int m = blockIdx.x * 32 + tx;
    float acc = 0.0f;
    for (int h0 = 0; h0 < 512; h0 += 32) {
        As[ty][tx] = g_A[n * 512 + h0 + tx];
        Bs[ty][tx] = g_B[(blockIdx.x * 32 + ty) * 512 + h0 + tx];
        if (ty == 0) w2s[tx] = W2[h0 + tx];
        __syncthreads();
#pragma unroll
        for (int hh = 0; hh < 32; hh++) {
            float v = As[ty][hh] + Bs[tx][hh];
            acc += tanh_(v) * w2s[hh];
        }
        __syncthreads();
    }
    float val = acc + b2[0];
    if (n == m) val = 0.0f;
    g_scores[n * 512 + m] = val;
}

// ---------------------------------------------------------------------------
// 5) column sums (axis 0)
// ---------------------------------------------------------------------------
__global__ void k_colsum() {
    int m = blockIdx.x * blockDim.x + threadIdx.x;   // <<<4,128>>>
    float s = 0.0f;
    for (int n = 0; n < SEQ; n++)
        s += g_scores[n * 512 + m];
    g_colsum[m] = s;
}

// ---------------------------------------------------------------------------
// 6) divide by colsum, then row softmax (axis 1)
// ---------------------------------------------------------------------------
__global__ void k_softmax(float* __restrict__ out) {
    __shared__ float red[512];
    int n = blockIdx.x, m = threadIdx.x;  // <<<512,512>>>
    float v = g_scores[n * 512 + m] / g_colsum[m];

    red[m] = v;
    __syncthreads();
    for (int off = 256; off > 0; off >>= 1) {
        if (m < off) red[m] = fmaxf(red[m], red[m + off]);
        __syncthreads();
    }
    float mx = red[0];
    __syncthreads();

    float p = __expf(v - mx);
    red[m] = p;
    __syncthreads();
    for (int off = 256; off > 0; off >>= 1) {
        if (m < off) red[m] = red[m] + red[m + off];
        __syncthreads();
    }
    float sum = red[0];
    out[n * 512 + m] = p / sum;
}

// ---------------------------------------------------------------------------
// launch — ONLY kernel launches.
// ---------------------------------------------------------------------------
extern "C" void kernel_launch(void* const* d_in, const int* in_sizes, int n_in,
                              void* d_out, int out_size) {
    const int*   word_ids = (const int*)d_in[0];
    const int*   tag_ids  = (const int*)d_in[1];
    const float* wemb     = (const float*)d_in[2];
    const float* temb     = (const float*)d_in[3];
    const float* h0       = (const float*)d_in[4];
    const float* c0       = (const float*)d_in[5];
    const float* Wih_l0f  = (const float*)d_in[6];
    const float* Whh_l0f  = (const float*)d_in[7];
    const float* bih_l0f  = (const float*)d_in[8];
    const float* bhh_l0f  = (const float*)d_in[9];
    const float* Wih_l0b  = (const float*)d_in[10];
    const float* Whh_l0b  = (const float*)d_in[11];
    const float* bih_l0b  = (const float*)d_in[12];
    const float* bhh_l0b  = (const float*)d_in[13];
    const float* Wih_l1f  = (const float*)d_in[14];
    const float* Whh_l1f  = (const float*)d_in[15];
    const float* bih_l1f  = (const float*)d_in[16];
    const float* bhh_l1f  = (const float*)d_in[17];
    const float* Wih_l1b  = (const float*)d_in[18];
    const float* Whh_l1b  = (const float*)d_in[19];
    const float* bih_l1b  = (const float*)d_in[20];
    const float* bhh_l1b  = (const float*)d_in[21];
    const float* W1       = (const float*)d_in[22];
    const float* b1       = (const float*)d_in[23];
    const float* W2       = (const float*)d_in[24];
    const float* b2       = (const float*)d_in[25];
    float* out = (float*)d_out;

    dim3 gblk(32, 32), ggrd(16, 16);
    const float* nul = (const float*)0;

    // embeddings
    k_embed<<<512, 128>>>(word_ids, tag_ids, wemb, temb);

    // layer 0: pre-activations + recurrence
    k_gemm<<<ggrd, gblk>>>(BUF_X, H, Wih_l0f, H, 0, bih_l0f, bhh_l0f, BUF_PREF, H);
    k_gemm<<<ggrd, gblk>>>(BUF_X, H, Wih_l0b, H, 0, bih_l0b, bhh_l0b, BUF_PREB, H);
    k_recur<<<8, 128>>>(0, Whh_l0f, Whh_l0b, h0, c0);

    // layer 1: pre-activations + recurrence
    k_gemm<<<ggrd, gblk>>>(BUF_H0OUT, D2, Wih_l1f, D2, 0, bih_l1f, bhh_l1f, BUF_PREF, D2);
    k_gemm<<<ggrd, gblk>>>(BUF_H0OUT, D2, Wih_l1b, D2, 0, bih_l1b, bhh_l1b, BUF_PREB, D2);
    k_recur<<<8, 128>>>(1, Whh_l1f, Whh_l1b, h0, c0);

    // MLP projections: A = h@W1[:, :256].T + b1 ; B = h@W1[:, 256:].T
    k_gemm<<<ggrd, gblk>>>(BUF_H1OUT, D2, W1, 512, 0,   b1,  nul, BUF_A, D2);
    k_gemm<<<ggrd, gblk>>>(BUF_H1OUT, D2, W1, 512, 256, nul, nul, BUF_B, D2);

    // pairwise scores, normalize, softmax
    k_pairwise<<<ggrd, gblk>>>(W2, b2);
    k_colsum<<<4, 128>>>();
    k_softmax<<<512, 512>>>(out);
}

// round 4
// speedup vs baseline: 7.0888x; 1.5840x over previous
#include <cuda_runtime.h>
#include <cuda_bf16.h>
#include <cstdint>

// ---------------------------------------------------------------------------
// DependencyParseModel: 2-layer BiLSTM (SEQ=512, H=128) -> pairwise tanh MLP
// scorer (512^3) -> column normalize -> row softmax.
//
// Round 4: recurrence = 2-CTA cluster, 256 thr/CTA, weights ALL in registers
// (packed f32x2), distributed per-thread mbarrier arrives (release.cluster),
// cta-scope acquire spin-waits, one __syncthreads per step.
// ---------------------------------------------------------------------------

#define SEQ 512
#define H   128
#define G4  512      // 4*H gates
#define D2  256      // 2*H concat

// ---- device scratch ----
__device__ float g_x[SEQ * H];
__device__ float g_pre[2][SEQ * G4];
__device__ float g_h0out[SEQ * D2];
__device__ float g_h1out[SEQ * D2];
__device__ float g_A[SEQ * 512];
__device__ float g_B[SEQ * 512];
__device__ float g_scores[SEQ * SEQ];
__device__ float g_colsum[SEQ];

#define BUF_X     0
#define BUF_PREF  1
#define BUF_PREB  2
#define BUF_H0OUT 3
#define BUF_H1OUT 4
#define BUF_A     5
#define BUF_B     6

__device__ __forceinline__ float* selbuf(int s) {
    switch (s) {
        case BUF_X:     return g_x;
        case BUF_PREF:  return g_pre[0];
        case BUF_PREB:  return g_pre[1];
        case BUF_H0OUT: return g_h0out;
        case BUF_H1OUT: return g_h1out;
        case BUF_A:     return g_A;
        default:        return g_B;
    }
}

// ---- math helpers ----
__device__ __forceinline__ float sigmoid_(float x) {
    float e = __expf(-x);
    return __fdividef(1.0f, 1.0f + e);
}
__device__ __forceinline__ float tanh_(float x) {
    float ax = fabsf(x);
    float e  = __expf(-2.0f * ax);
    float r  = __fdividef(1.0f - e, 1.0f + e);
    return __int_as_float(__float_as_int(r) | (__float_as_int(x) & 0x80000000));
}

// ---- packed f32x2 helpers ----
__device__ __forceinline__ unsigned long long pack2_(float lo, float hi) {
    unsigned long long r;
    asm("mov.b64 %0, {%1, %2};" : "=l"(r) : "f"(lo), "f"(hi));
    return r;
}
__device__ __forceinline__ void ffma2_(unsigned long long& acc,
                                       unsigned long long a, unsigned long long b) {
    asm("fma.rn.f32x2 %0, %1, %2, %0;" : "+l"(acc) : "l"(a), "l"(b));
}
__device__ __forceinline__ float hsum2_(unsigned long long v) {
    float lo, hi;
    asm("mov.b64 {%0, %1}, %2;" : "=f"(lo), "=f"(hi) : "l"(v));
    return lo + hi;
}

// ---- cluster / mbarrier helpers ----
__device__ __forceinline__ uint32_t s2u_(const void* p) {
    uint32_t a;
    asm("{ .reg .u64 t; cvta.to.shared.u64 t, %1; cvt.u32.u64 %0, t; }"
        : "=r"(a) : "l"(p));
    return a;
}
__device__ __forceinline__ uint32_t mapa_(uint32_t a, uint32_t rank) {
    uint32_t o;
    asm("mapa.shared::cluster.u32 %0, %1, %2;" : "=r"(o) : "r"(a), "r"(rank));
    return o;
}
__device__ __forceinline__ void st_remote_f32(uint32_t a, float v) {
    asm volatile("st.shared::cluster.f32 [%0], %1;" :: "r"(a), "f"(v) : "memory");
}
__device__ __forceinline__ void mbar_init_(uint32_t a, uint32_t cnt) {
    asm volatile("mbarrier.init.shared.b64 [%0], %1;" :: "r"(a), "r"(cnt) : "memory");
}
__device__ __forceinline__ void mbar_arrive_local(uint32_t a) {
    asm volatile("mbarrier.arrive.release.cta.shared::cta.b64 _, [%0];"
                 :: "r"(a) : "memory");
}
__device__ __forceinline__ void mbar_arrive_remote(uint32_t a) {
    asm volatile("mbarrier.arrive.release.cluster.shared::cluster.b64 _, [%0];"
                 :: "r"(a) : "memory");
}
__device__ __forceinline__ void mbar_wait_(uint32_t a, uint32_t par) {
    asm volatile(
        "{\n\t.reg .pred P;\n\t"
        "WL_%=:\n\t"
        "mbarrier.try_wait.parity.acquire.cta.shared::cta.b64 P, [%0], %1, 0x989680;\n\t"
        "@!P bra WL_%=;\n\t}"
        :: "r"(a), "r"(par) : "memory");
}

// ---------------------------------------------------------------------------
// 1) embedding gather
// ---------------------------------------------------------------------------
__global__ void k_embed(const int* __restrict__ wid, const int* __restrict__ tid,
                        const float* __restrict__ wemb, const float* __restrict__ temb) {
    int t = blockIdx.x, k = threadIdx.x;   // <<<512,128>>>
    float v;
    if (k < 100) v = wemb[wid[t] * 100 + k];
    else         v = temb[tid[t] * 28 + (k - 100)];
    g_x[t * H + k] = v;
}

// ---------------------------------------------------------------------------
// 2) fused dual GEMM: z = blockIdx.z selects config.
//    C[512][512] = X[512][K] @ W[512][K]^T (+ b1 + b2)
// ---------------------------------------------------------------------------
__global__ void k_gemm2(int srcSel, int ldx,
                        const float* __restrict__ Wz0, const float* __restrict__ Wz1,
                        int woff0, int woff1,
                        const float* b10, const float* b11,
                        const float* b20, const float* b21,
                        int dst0, int dst1, int K) {
    const int z = blockIdx.z;
    const float* W  = z ? Wz1 : Wz0;
    const int woff  = z ? woff1 : woff0;
    const float* b1 = z ? b11 : b10;
    const float* b2 = z ? b21 : b20;
    const float* X  = selbuf(srcSel);
    float*       C  = selbuf(z ? dst1 : dst0);

    __shared__ float Xs[32][33];
    __shared__ float Ws[32][33];
    int tx = threadIdx.x, ty = threadIdx.y;
    int row = blockIdx.y * 32 + ty;
    int col = blockIdx.x * 32 + tx;
    float acc = 0.0f;
    for (int k0 = 0; k0 < K; k0 += 32) {
        Xs[ty][tx] = X[row * ldx + k0 + tx];
        Ws[ty][tx] = W[(blockIdx.x * 32 + ty) * (K == 128 ? 128 : (ldx == D2 && woff0 == 0 && woff1 == 256 ? 512 : K)) + woff + k0 + tx];
        __syncthreads();
#pragma unroll
        for (int kk = 0; kk < 32; kk++)
            acc += Xs[ty][kk] * Ws[tx][kk];
        __syncthreads();
    }
    float b = 0.0f;
    if (b1) b += b1[col];
    if (b2) b += b2[col];
    C[row * 512 + col] = acc + b;
}

// ---------------------------------------------------------------------------
// 3) LSTM recurrence: grid 4, cluster 2. CTAs {0,1} = fwd cluster? No:
//    blocks 0,1 = forward cluster; blocks 2,3 = backward cluster.
//    Rank r owns units [64r, 64r+64). Thread t: gate = t>>6, ul = t&63,
//    gate row R = gate*128 + 64r + ul, weights in 64 packed f32x2 regs.
// ---------------------------------------------------------------------------
__global__ void __launch_bounds__(256, 1) __cluster_dims__(2, 1, 1)
k_recur(int layer, const float* __restrict__ Whh_f, const float* __restrict__ Whh_b,
        const float* __restrict__ h0, const float* __restrict__ c0) {
    const int d = blockIdx.x >> 1;          // 0 = forward, 1 = backward
    const int r = blockIdx.x & 1;           // cluster rank
    const int peer = r ^ 1;
    const int t = threadIdx.x;              // 0..255
    const int gate = t >> 6, ul = t & 63;
    const int R = gate * 128 + r * 64 + ul; // global gate row

    const float* __restrict__ Whh = d ? Whh_b : Whh_f;
    const float* __restrict__ pre = g_pre[d];
    float* __restrict__ out = layer ? g_h1out : g_h0out;

    __shared__ __align__(16) float h_s[2][H];
    __shared__ float gb[256];
    __shared__ __align__(8) unsigned long long mbar;

    const uint32_t mb_a = s2u_(&mbar);
    if (t == 0) mbar_init_(mb_a, 128);      // 64 local + 64 remote arrivals

    // weight row -> 64 packed f32x2 registers
    unsigned long long wpk[64];
    {
        const float4* Wr = (const float4*)(Whh + (size_t)R * H);
#pragma unroll
        for (int k4 = 0; k4 < 32; k4++) {
            float4 v = Wr[k4];
            wpk[2 * k4]     = pack2_(v.x, v.y);
            wpk[2 * k4 + 1] = pack2_(v.z, v.w);
        }
    }

    // init state (both CTAs hold the full h vector locally)
    const int row0 = (2 * layer + d) * H;
    if (t < H) h_s[0][t] = h0[row0 + t];
    float c = (t < 64) ? c0[row0 + r * 64 + t] : 0.0f;

    // precompute peer addresses
    const int u_mine = r * 64 + ul;
    const uint32_t ph[2] = { mapa_(s2u_(&h_s[0][u_mine]), (uint32_t)peer),
                             mapa_(s2u_(&h_s[1][u_mine]), (uint32_t)peer) };
    const uint32_t pmb   = mapa_(mb_a, (uint32_t)peer);

    __syncthreads();
    asm volatile("barrier.cluster.arrive.aligned;" ::: "memory");
    asm volatile("barrier.cluster.wait.aligned;" ::: "memory");

    for (int s = 0; s < SEQ; s++) {
        const int ti = d ? (SEQ - 1 - s) : s;
        const float pv = pre[(size_t)ti * G4 + R];   // LDG early, used late

        const ulonglong2* h2 = (const ulonglong2*)h_s[s & 1];
        unsigned long long a0 = 0ull, a1 = 0ull;
#pragma unroll
        for (int k = 0; k < 32; k++) {
            ulonglong2 hv = h2[k];                   // 16B broadcast LDS
            ffma2_(a0, wpk[2 * k],     hv.x);
            ffma2_(a1, wpk[2 * k + 1], hv.y);
        }
        gb[t] = hsum2_(a0) + hsum2_(a1) + pv;
        __syncthreads();                             // full gb visible

        if (t < 64) {
            float i_ = sigmoid_(gb[t]);
            float f_ = sigmoid_(gb[64 + t]);
            float gg = tanh_(gb[128 + t]);
            float o_ = sigmoid_(gb[192 + t]);
            c = f_ * c + i_ * gg;
            float h = o_ * tanh_(c);

            const int nxt = (s + 1) & 1;
            h_s[nxt][u_mine] = h;                    // local copy
            st_remote_f32(ph[nxt], h);               // peer copy
            out[(size_t)ti * D2 + d * H + u_mine] = h;

            mbar_arrive_local(mb_a);                 // orders local store
            mbar_arrive_remote(pmb);                 // orders remote store
        }
        mbar_wait_(mb_a, s & 1);                     // all 256 threads wait
    }
}

// ---------------------------------------------------------------------------
// 4) pairwise scorer
// ---------------------------------------------------------------------------
__global__ void k_pairwise(const float* __restrict__ W2, const float* __restrict__ b2) {
    __shared__ float As[32][33];
    __shared__ float Bs[32][33];
    __shared__ float w2s[32];
    int tx = threadIdx.x, ty = threadIdx.y;
    int n = blockIdx.y * 32 + ty;
    int m = blockIdx.x * 32 + tx;
    float acc = 0.0f;
    for (int h0 = 0; h0 < 512; h0 += 32) {
        As[ty][tx] = g_A[n * 512 + h0 + tx];
        Bs[ty][tx] = g_B[(blockIdx.x * 32 + ty) * 512 + h0 + tx];
        if (ty == 0) w2s[tx] = W2[h0 + tx];
        __syncthreads();
#pragma unroll
        for (int hh = 0; hh < 32; hh++) {
            float v = As[ty][hh] + Bs[tx][hh];
            acc += tanh_(v) * w2s[hh];
        }
        __syncthreads();
    }
    float val = acc + b2[0];
    if (n == m) val = 0.0f;
    g_scores[n * 512 + m] = val;
}

// ---------------------------------------------------------------------------
// 5) column sums
// ---------------------------------------------------------------------------
__global__ void k_colsum() {
    int m = blockIdx.x * blockDim.x + threadIdx.x;   // <<<4,128>>>
    float s = 0.0f;
    for (int n = 0; n < SEQ; n++)
        s += g_scores[n * 512 + m];
    g_colsum[m] = s;
}

// ---------------------------------------------------------------------------
// 6) normalize + row softmax
// ---------------------------------------------------------------------------
__global__ void k_softmax(float* __restrict__ out) {
    __shared__ float red[512];
    int n = blockIdx.x, m = threadIdx.x;  // <<<512,512>>>
    float v = g_scores[n * 512 + m] / g_colsum[m];

    red[m] = v;
    __syncthreads();
    for (int off = 256; off > 0; off >>= 1) {
        if (m < off) red[m] = fmaxf(red[m], red[m + off]);
        __syncthreads();
    }
    float mx = red[0];
    __syncthreads();

    float p = __expf(v - mx);
    red[m] = p;
    __syncthreads();
    for (int off = 256; off > 0; off >>= 1) {
        if (m < off) red[m] = red[m] + red[m + off];
        __syncthreads();
    }
    float sum = red[0];
    out[n * 512 + m] = p / sum;
}

// ---------------------------------------------------------------------------
// launch — ONLY kernel launches.
// ---------------------------------------------------------------------------
extern "C" void kernel_launch(void* const* d_in, const int* in_sizes, int n_in,
                              void* d_out, int out_size) {
    const int*   word_ids = (const int*)d_in[0];
    const int*   tag_ids  = (const int*)d_in[1];
    const float* wemb     = (const float*)d_in[2];
    const float* temb     = (const float*)d_in[3];
    const float* h0       = (const float*)d_in[4];
    const float* c0       = (const float*)d_in[5];
    const float* Wih_l0f  = (const float*)d_in[6];
    const float* Whh_l0f  = (const float*)d_in[7];
    const float* bih_l0f  = (const float*)d_in[8];
    const float* bhh_l0f  = (const float*)d_in[9];
    const float* Wih_l0b  = (const float*)d_in[10];
    const float* Whh_l0b  = (const float*)d_in[11];
    const float* bih_l0b  = (const float*)d_in[12];
    const float* bhh_l0b  = (const float*)d_in[13];
    const float* Wih_l1f  = (const float*)d_in[14];
    const float* Whh_l1f  = (const float*)d_in[15];
    const float* bih_l1f  = (const float*)d_in[16];
    const float* bhh_l1f  = (const float*)d_in[17];
    const float* Wih_l1b  = (const float*)d_in[18];
    const float* Whh_l1b  = (const float*)d_in[19];
    const float* bih_l1b  = (const float*)d_in[20];
    const float* bhh_l1b  = (const float*)d_in[21];
    const float* W1       = (const float*)d_in[22];
    const float* b1       = (const float*)d_in[23];
    const float* W2       = (const float*)d_in[24];
    const float* b2       = (const float*)d_in[25];
    float* out = (float*)d_out;

    dim3 gblk(32, 32);
    dim3 ggrd2(16, 16, 2);
    const float* nul = (const float*)0;

    k_embed<<<512, 128>>>(word_ids, tag_ids, wemb, temb);

    // layer 0: fused f/b pre-activation GEMMs + recurrence
    k_gemm2<<<ggrd2, gblk>>>(BUF_X, H, Wih_l0f, Wih_l0b, 0, 0,
                             bih_l0f, bih_l0b, bhh_l0f, bhh_l0b,
                             BUF_PREF, BUF_PREB, H);
    k_recur<<<4, 256>>>(0, Whh_l0f, Whh_l0b, h0, c0);

    // layer 1
    k_gemm2<<<ggrd2, gblk>>>(BUF_H0OUT, D2, Wih_l1f, Wih_l1b, 0, 0,
                             bih_l1f, bih_l1b, bhh_l1f, bhh_l1b,
                             BUF_PREF, BUF_PREB, D2);
    k_recur<<<4, 256>>>(1, Whh_l1f, Whh_l1b, h0, c0);

    // MLP projections: A = h@W1[:, :256].T + b1 ; B = h@W1[:, 256:].T
    k_gemm2<<<ggrd2, gblk>>>(BUF_H1OUT, D2, W1, W1, 0, 256,
                             b1, nul, nul, nul,
                             BUF_A, BUF_B, D2);

    k_pairwise<<<dim3(16, 16), gblk>>>(W2, b2);
    k_colsum<<<4, 128>>>();
    k_softmax<<<512, 512>>>(out);
}

// round 5
// speedup vs baseline: 7.4664x; 1.0533x over previous
#include <cuda_runtime.h>
#include <cuda_bf16.h>
#include <cstdint>

// ---------------------------------------------------------------------------
// DependencyParseModel: 2-layer BiLSTM (SEQ=512, H=128) -> pairwise tanh MLP
// scorer (512^3) -> column normalize -> row softmax.
//
// Round 5:
//   - recurrence: 2-CTA cluster, weights in registers (f32x2). Exchange is
//     weak stores + ONE elected arrive pair per CTA per step (mbar count=2)
//     instead of 128 serialized barrier ops.
//   - GEMM: 2x2 register micro-tile (1 LDS per FFMA).
//   - coalesced colsum, shuffle-based softmax.
// ---------------------------------------------------------------------------

#define SEQ 512
#define H   128
#define G4  512      // 4*H gates
#define D2  256      // 2*H concat

// ---- device scratch ----
__device__ float g_x[SEQ * H];
__device__ float g_pre[2][SEQ * G4];
__device__ float g_h0out[SEQ * D2];
__device__ float g_h1out[SEQ * D2];
__device__ float g_A[SEQ * 512];
__device__ float g_B[SEQ * 512];
__device__ float g_scores[SEQ * SEQ];
__device__ float g_colsum[SEQ];

#define BUF_X     0
#define BUF_PREF  1
#define BUF_PREB  2
#define BUF_H0OUT 3
#define BUF_H1OUT 4
#define BUF_A     5
#define BUF_B     6

__device__ __forceinline__ float* selbuf(int s) {
    switch (s) {
        case BUF_X:     return g_x;
        case BUF_PREF:  return g_pre[0];
        case BUF_PREB:  return g_pre[1];
        case BUF_H0OUT: return g_h0out;
        case BUF_H1OUT: return g_h1out;
        case BUF_A:     return g_A;
        default:        return g_B;
    }
}

// ---- math helpers ----
__device__ __forceinline__ float sigmoid_(float x) {
    float e = __expf(-x);
    return __fdividef(1.0f, 1.0f + e);
}
__device__ __forceinline__ float tanh_(float x) {
    float ax = fabsf(x);
    float e  = __expf(-2.0f * ax);
    float r  = __fdividef(1.0f - e, 1.0f + e);
    return __int_as_float(__float_as_int(r) | (__float_as_int(x) & 0x80000000));
}

// ---- packed f32x2 helpers ----
__device__ __forceinline__ unsigned long long pack2_(float lo, float hi) {
    unsigned long long r;
    asm("mov.b64 %0, {%1, %2};" : "=l"(r) : "f"(lo), "f"(hi));
    return r;
}
__device__ __forceinline__ void ffma2_(unsigned long long& acc,
                                       unsigned long long a, unsigned long long b) {
    asm("fma.rn.f32x2 %0, %1, %2, %0;" : "+l"(acc) : "l"(a), "l"(b));
}
__device__ __forceinline__ float hsum2_(unsigned long long v) {
    float lo, hi;
    asm("mov.b64 {%0, %1}, %2;" : "=f"(lo), "=f"(hi) : "l"(v));
    return lo + hi;
}

// ---- cluster / mbarrier helpers ----
__device__ __forceinline__ uint32_t s2u_(const void* p) {
    uint32_t a;
    asm("{ .reg .u64 t; cvta.to.shared.u64 t, %1; cvt.u32.u64 %0, t; }"
        : "=r"(a) : "l"(p));
    return a;
}
__device__ __forceinline__ uint32_t mapa_(uint32_t a, uint32_t rank) {
    uint32_t o;
    asm("mapa.shared::cluster.u32 %0, %1, %2;" : "=r"(o) : "r"(a), "r"(rank));
    return o;
}
__device__ __forceinline__ void st_remote_f32(uint32_t a, float v) {
    asm volatile("st.shared::cluster.f32 [%0], %1;" :: "r"(a), "f"(v) : "memory");
}
__device__ __forceinline__ void mbar_init_(uint32_t a, uint32_t cnt) {
    asm volatile("mbarrier.init.shared.b64 [%0], %1;" :: "r"(a), "r"(cnt) : "memory");
}
__device__ __forceinline__ void mbar_arrive_local(uint32_t a) {
    asm volatile("mbarrier.arrive.release.cta.shared::cta.b64 _, [%0];"
                 :: "r"(a) : "memory");
}
__device__ __forceinline__ void mbar_arrive_remote(uint32_t a) {
    asm volatile("mbarrier.arrive.release.cluster.shared::cluster.b64 _, [%0];"
                 :: "r"(a) : "memory");
}
__device__ __forceinline__ void mbar_wait_(uint32_t a, uint32_t par) {
    asm volatile(
        "{\n\t.reg .pred P;\n\t"
        "WL_%=:\n\t"
        "mbarrier.try_wait.parity.acquire.cta.shared::cta.b64 P, [%0], %1, 0x989680;\n\t"
        "@!P bra WL_%=;\n\t}"
        :: "r"(a), "r"(par) : "memory");
}

// ---------------------------------------------------------------------------
// 1) embedding gather
// ---------------------------------------------------------------------------
__global__ void k_embed(const int* __restrict__ wid, const int* __restrict__ tid,
                        const float* __restrict__ wemb, const float* __restrict__ temb) {
    int t = blockIdx.x, k = threadIdx.x;   // <<<512,128>>>
    float v;
    if (k < 100) v = wemb[wid[t] * 100 + k];
    else         v = temb[tid[t] * 28 + (k - 100)];
    g_x[t * H + k] = v;
}

// ---------------------------------------------------------------------------
// 2) fused dual GEMM, 2x2 micro-tile. block (16,16), grid (16,16,2).
//    C[512][512] = X[512][K] @ W[512][K]^T (+ b1 + b2)
// ---------------------------------------------------------------------------
__global__ void __launch_bounds__(256)
k_gemm2(int srcSel, int ldx,
        const float* __restrict__ Wz0, const float* __restrict__ Wz1,
        int woff0, int woff1, int ldw,
        const float* b10, const float* b11,
        const float* b20, const float* b21,
        int dst0, int dst1, int K) {
    const int z = blockIdx.z;
    const float* __restrict__ W  = z ? Wz1 : Wz0;
    const int woff  = z ? woff1 : woff0;
    const float* b1 = z ? b11 : b10;
    const float* b2 = z ? b21 : b20;
    const float* __restrict__ X  = selbuf(srcSel);
    float*       __restrict__ C  = selbuf(z ? dst1 : dst0);

    __shared__ float Xs[32][33];
    __shared__ float Ws[32][33];
    const int tx = threadIdx.x, ty = threadIdx.y;      // 16x16
    const int lid = ty * 16 + tx;                       // 0..255
    const int row0 = blockIdx.y * 32, col0 = blockIdx.x * 32;

    float a00 = 0.f, a01 = 0.f, a10 = 0.f, a11 = 0.f;
    for (int k0 = 0; k0 < K; k0 += 32) {
#pragma unroll
        for (int i = 0; i < 4; i++) {
            int e = lid + i * 256, rr = e >> 5, cc = e & 31;
            Xs[rr][cc] = X[(row0 + rr) * ldx + k0 + cc];
            Ws[rr][cc] = W[(col0 + rr) * ldw + woff + k0 + cc];
        }
        __syncthreads();
#pragma unroll
        for (int kk = 0; kk < 32; kk++) {
            float x0 = Xs[2 * ty][kk],  x1 = Xs[2 * ty + 1][kk];
            float w0 = Ws[2 * tx][kk],  w1 = Ws[2 * tx + 1][kk];
            a00 += x0 * w0; a01 += x0 * w1;
            a10 += x1 * w0; a11 += x1 * w1;
        }
        __syncthreads();
    }
    const int r0 = row0 + 2 * ty, c0 = col0 + 2 * tx;
    float bb0 = 0.f, bb1 = 0.f;
    if (b1) { bb0 += b1[c0]; bb1 += b1[c0 + 1]; }
    if (b2) { bb0 += b2[c0]; bb1 += b2[c0 + 1]; }
    C[r0 * 512 + c0]           = a00 + bb0;
    C[r0 * 512 + c0 + 1]       = a01 + bb1;
    C[(r0 + 1) * 512 + c0]     = a10 + bb0;
    C[(r0 + 1) * 512 + c0 + 1] = a11 + bb1;
}

// ---------------------------------------------------------------------------
// 3) LSTM recurrence: grid 4, cluster 2. Blocks {0,1} = forward cluster,
//    {2,3} = backward. Rank r owns units [64r, 64r+64). Thread t computes
//    gate row R = (t>>6)*128 + 64r + (t&63); weights in 64 f32x2 registers.
//    Exchange: weak local+remote stores, syncthreads, ONE elected
//    arrive(local)+arrive(remote) per CTA; mbar arrive count = 2.
// ---------------------------------------------------------------------------
__global__ void __launch_bounds__(256, 1) __cluster_dims__(2, 1, 1)
k_recur(int layer, const float* __restrict__ Whh_f, const float* __restrict__ Whh_b,
        const float* __restrict__ h0, const float* __restrict__ c0) {
    const int d = blockIdx.x >> 1;
    const int r = blockIdx.x & 1;
    const int peer = r ^ 1;
    const int t = threadIdx.x;              // 0..255
    const int gate = t >> 6, ul = t & 63;
    const int R = gate * 128 + r * 64 + ul;

    const float* __restrict__ Whh = d ? Whh_b : Whh_f;
    const float* __restrict__ pre = g_pre[d];
    float* __restrict__ out = layer ? g_h1out : g_h0out;

    __shared__ __align__(16) float h_s[2][H];
    __shared__ float gb[256];
    __shared__ __align__(8) unsigned long long mbar;

    const uint32_t mb_a = s2u_(&mbar);
    if (t == 0) mbar_init_(mb_a, 2);        // 1 local elected + 1 peer elected

    // weight row -> 64 packed f32x2 registers
    unsigned long long wpk[64];
    {
        const float4* Wr = (const float4*)(Whh + (size_t)R * H);
#pragma unroll
        for (int k4 = 0; k4 < 32; k4++) {
            float4 v = Wr[k4];
            wpk[2 * k4]     = pack2_(v.x, v.y);
            wpk[2 * k4 + 1] = pack2_(v.z, v.w);
        }
    }

    const int row0 = (2 * layer + d) * H;
    if (t < H) h_s[0][t] = h0[row0 + t];
    float c = (t < 64) ? c0[row0 + r * 64 + t] : 0.0f;

    const int u_mine = r * 64 + ul;
    const uint32_t ph[2] = { mapa_(s2u_(&h_s[0][u_mine]), (uint32_t)peer),
                             mapa_(s2u_(&h_s[1][u_mine]), (uint32_t)peer) };
    const uint32_t pmb   = mapa_(mb_a, (uint32_t)peer);

    __syncthreads();
    asm volatile("barrier.cluster.arrive.aligned;" ::: "memory");
    asm volatile("barrier.cluster.wait.aligned;" ::: "memory");

    for (int s = 0; s < SEQ; s++) {
        const int ti = d ? (SEQ - 1 - s) : s;
        const float pv = pre[(size_t)ti * G4 + R];   // issued early, used late

        const ulonglong2* h2 = (const ulonglong2*)h_s[s & 1];
        unsigned long long a0 = 0ull, a1 = 0ull;
#pragma unroll
        for (int k = 0; k < 32; k++) {
            ulonglong2 hv = h2[k];                   // 16B broadcast LDS
            ffma2_(a0, wpk[2 * k],     hv.x);
            ffma2_(a1, wpk[2 * k + 1], hv.y);
        }
        gb[t] = hsum2_(a0) + hsum2_(a1) + pv;
        __syncthreads();                             // gb fully visible

        if (t < 64) {
            float i_ = sigmoid_(gb[t]);
            float f_ = sigmoid_(gb[64 + t]);
            float gg = tanh_(gb[128 + t]);
            float o_ = sigmoid_(gb[192 + t]);
            c = f_ * c + i_ * gg;
            float h = o_ * tanh_(c);

            const int nxt = (s + 1) & 1;
            h_s[nxt][u_mine] = h;                    // local (weak)
            st_remote_f32(ph[nxt], h);               // peer  (weak)
            out[(size_t)ti * D2 + d * H + u_mine] = h;
        }
        __syncthreads();                             // all stores program-ordered
        if (t == 0) {
            mbar_arrive_local(mb_a);                 // release.cta: local stores
            mbar_arrive_remote(pmb);                 // release.cluster: remote stores
        }
        mbar_wait_(mb_a, s & 1);
    }
}

// ---------------------------------------------------------------------------
// 4) pairwise scorer
// ---------------------------------------------------------------------------
__global__ void k_pairwise(const float* __restrict__ W2, const float* __restrict__ b2) {
    __shared__ float As[32][33];
    __shared__ float Bs[32][33];
    __shared__ float w2s[32];
    int tx = threadIdx.x, ty = threadIdx.y;
    int n = blockIdx.y * 32 + ty;
    int m = blockIdx.x * 32 + tx;
    float acc = 0.0f;
    for (int h0 = 0; h0 < 512; h0 += 32) {
        As[ty][tx] = g_A[n * 512 + h0 + tx];
        Bs[ty][tx] = g_B[(blockIdx.x * 32 + ty) * 512 + h0 + tx];
        if (ty == 0) w2s[tx] = W2[h0 + tx];
        __syncthreads();
#pragma unroll
        for (int hh = 0; hh < 32; hh++) {
            float v = As[ty][hh] + Bs[tx][hh];
            acc += tanh_(v) * w2s[hh];
        }
        __syncthreads();
    }
    float val = acc + b2[0];
    if (n == m) val = 0.0f;
    g_scores[n * 512 + m] = val;
}

// ---------------------------------------------------------------------------
// 5) column sums — coalesced: block = 64 cols x 16 row-lanes, grid 8
// ---------------------------------------------------------------------------
__global__ void __launch_bounds__(1024) k_colsum() {
    __shared__ float red[1024];
    const int cc = threadIdx.x & 63;
    const int rg = threadIdx.x >> 6;                 // 0..15
    const int c  = blockIdx.x * 64 + cc;
    float s = 0.0f;
    for (int n = rg; n < SEQ; n += 16)
        s += g_scores[n * 512 + c];
    red[threadIdx.x] = s;
    __syncthreads();
    for (int off = 512; off >= 64; off >>= 1) {
        if (threadIdx.x < off) red[threadIdx.x] += red[threadIdx.x + off];
        __syncthreads();
    }
    if (threadIdx.x < 64) g_colsum[c] = red[threadIdx.x];
}

// ---------------------------------------------------------------------------
// 6) normalize + row softmax (shuffle reductions)
// ---------------------------------------------------------------------------
__global__ void __launch_bounds__(512) k_softmax(float* __restrict__ out) {
    __shared__ float sred[16];
    const int n = blockIdx.x, m = threadIdx.x;
    const int lane = m & 31, wid = m >> 5;
    float v = g_scores[n * 512 + m] / g_colsum[m];

    float wm = v;
#pragma unroll
    for (int off = 16; off > 0; off >>= 1)
        wm = fmaxf(wm, __shfl_xor_sync(0xffffffffu, wm, off));
    if (lane == 0) sred[wid] = wm;
    __syncthreads();
    if (wid == 0) {
        float x = sred[lane & 15];
#pragma unroll
        for (int off = 8; off > 0; off >>= 1)
            x = fmaxf(x, __shfl_xor_sync(0xffffffffu, x, off));
        if (lane == 0) sred[0] = x;
    }
    __syncthreads();
    const float mx = sred[0];
    __syncthreads();

    float p = __expf(v - mx);
    float ws = p;
#pragma unroll
    for (int off = 16; off > 0; off >>= 1)
        ws += __shfl_xor_sync(0xffffffffu, ws, off);
    if (lane == 0) sred[wid] = ws;
    __syncthreads();
    if (wid == 0) {
        float x = sred[lane & 15];
#pragma unroll
        for (int off = 8; off > 0; off >>= 1)
            x += __shfl_xor_sync(0xffffffffu, x, off);
        if (lane == 0) sred[0] = x;
    }
    __syncthreads();
    out[n * 512 + m] = p / sred[0];
}

// ---------------------------------------------------------------------------
// launch — ONLY kernel launches.
// ---------------------------------------------------------------------------
extern "C" void kernel_launch(void* const* d_in, const int* in_sizes, int n_in,
                              void* d_out, int out_size) {
    const int*   word_ids = (const int*)d_in[0];
    const int*   tag_ids  = (const int*)d_in[1];
    const float* wemb     = (const float*)d_in[2];
    const float* temb     = (const float*)d_in[3];
    const float* h0       = (const float*)d_in[4];
    const float* c0       = (const float*)d_in[5];
    const float* Wih_l0f  = (const float*)d_in[6];
    const float* Whh_l0f  = (const float*)d_in[7];
    const float* bih_l0f  = (const float*)d_in[8];
    const float* bhh_l0f  = (const float*)d_in[9];
    const float* Wih_l0b  = (const float*)d_in[10];
    const float* Whh_l0b  = (const float*)d_in[11];
    const float* bih_l0b  = (const float*)d_in[12];
    const float* bhh_l0b  = (const float*)d_in[13];
    const float* Wih_l1f  = (const float*)d_in[14];
    const float* Whh_l1f  = (const float*)d_in[15];
    const float* bih_l1f  = (const float*)d_in[16];
    const float* bhh_l1f  = (const float*)d_in[17];
    const float* Wih_l1b  = (const float*)d_in[18];
    const float* Whh_l1b  = (const float*)d_in[19];
    const float* bih_l1b  = (const float*)d_in[20];
    const float* bhh_l1b  = (const float*)d_in[21];
    const float* W1       = (const float*)d_in[22];
    const float* b1       = (const float*)d_in[23];
    const float* W2       = (const float*)d_in[24];
    const float* b2       = (const float*)d_in[25];
    float* out = (float*)d_out;

    dim3 gblk(16, 16);
    dim3 ggrd2(16, 16, 2);
    const float* nul = (const float*)0;

    k_embed<<<512, 128>>>(word_ids, tag_ids, wemb, temb);

    // layer 0
    k_gemm2<<<ggrd2, gblk>>>(BUF_X, H, Wih_l0f, Wih_l0b, 0, 0, 128,
                             bih_l0f, bih_l0b, bhh_l0f, bhh_l0b,
                             BUF_PREF, BUF_PREB, H);
    k_recur<<<4, 256>>>(0, Whh_l0f, Whh_l0b, h0, c0);

    // layer 1
    k_gemm2<<<ggrd2, gblk>>>(BUF_H0OUT, D2, Wih_l1f, Wih_l1b, 0, 0, 256,
                             bih_l1f, bih_l1b, bhh_l1f, bhh_l1b,
                             BUF_PREF, BUF_PREB, D2);
    k_recur<<<4, 256>>>(1, Whh_l1f, Whh_l1b, h0, c0);

    // MLP projections: A = h@W1[:, :256].T + b1 ; B = h@W1[:, 256:].T
    k_gemm2<<<ggrd2, gblk>>>(BUF_H1OUT, D2, W1, W1, 0, 256, 512,
                             b1, nul, nul, nul,
                             BUF_A, BUF_B, D2);

    k_pairwise<<<dim3(16, 16), dim3(32, 32)>>>(W2, b2);
    k_colsum<<<8, 1024>>>();
    k_softmax<<<512, 512>>>(out);
}

// round 7
// speedup vs baseline: 9.7970x; 1.3121x over previous
#include <cuda_runtime.h>
#include <cuda_bf16.h>
#include <cstdint>

// ---------------------------------------------------------------------------
// DependencyParseModel: 2-layer BiLSTM (SEQ=512, H=128) -> pairwise tanh MLP
// scorer (512^3) -> column normalize -> row softmax.
//
// Round 7 == Round 6 resubmission (R6 never ran: GPU broker timeout).
// Recurrence (2-CTA cluster, weights in registers):
//   thread = (unit, K-quarter). Gate sums via shfl (no SMEM round trip, no
//   pre-activation barrier). Activations branchless (sigmoid via tanh) on
//   all warps. h exchange via st.async + mbarrier expect_tx (single
//   instruction store+signal). One __syncthreads per step.
// ---------------------------------------------------------------------------

#define SEQ 512
#define H   128
#define G4  512      // 4*H gates
#define D2  256      // 2*H concat

// ---- device scratch ----
__device__ float g_x[SEQ * H];
__device__ float g_pre[2][SEQ * G4];
__device__ float g_h0out[SEQ * D2];
__device__ float g_h1out[SEQ * D2];
__device__ float g_A[SEQ * 512];
__device__ float g_B[SEQ * 512];
__device__ float g_scores[SEQ * SEQ];
__device__ float g_colsum[SEQ];

#define BUF_X     0
#define BUF_PREF  1
#define BUF_PREB  2
#define BUF_H0OUT 3
#define BUF_H1OUT 4
#define BUF_A     5
#define BUF_B     6

__device__ __forceinline__ float* selbuf(int s) {
    switch (s) {
        case BUF_X:     return g_x;
        case BUF_PREF:  return g_pre[0];
        case BUF_PREB:  return g_pre[1];
        case BUF_H0OUT: return g_h0out;
        case BUF_H1OUT: return g_h1out;
        case BUF_A:     return g_A;
        default:        return g_B;
    }
}

// ---- math helpers ----
__device__ __forceinline__ float tanh_(float x) {
    float ax = fabsf(x);
    float e  = __expf(-2.0f * ax);
    float r  = __fdividef(1.0f - e, 1.0f + e);
    return __int_as_float(__float_as_int(r) | (__float_as_int(x) & 0x80000000));
}

// ---- packed f32x2 helpers ----
__device__ __forceinline__ unsigned long long pack2_(float lo, float hi) {
    unsigned long long r;
    asm("mov.b64 %0, {%1, %2};" : "=l"(r) : "f"(lo), "f"(hi));
    return r;
}
__device__ __forceinline__ void ffma2_(unsigned long long& acc,
                                       unsigned long long a, unsigned long long b) {
    asm("fma.rn.f32x2 %0, %1, %2, %0;" : "+l"(acc) : "l"(a), "l"(b));
}
__device__ __forceinline__ float hsum2_(unsigned long long v) {
    float lo, hi;
    asm("mov.b64 {%0, %1}, %2;" : "=f"(lo), "=f"(hi) : "l"(v));
    return lo + hi;
}

// ---- cluster / mbarrier helpers ----
__device__ __forceinline__ uint32_t s2u_(const void* p) {
    uint32_t a;
    asm("{ .reg .u64 t; cvta.to.shared.u64 t, %1; cvt.u32.u64 %0, t; }"
        : "=r"(a) : "l"(p));
    return a;
}
__device__ __forceinline__ uint32_t mapa_(uint32_t a, uint32_t rank) {
    uint32_t o;
    asm("mapa.shared::cluster.u32 %0, %1, %2;" : "=r"(o) : "r"(a), "r"(rank));
    return o;
}
__device__ __forceinline__ void mbar_init_(uint32_t a, uint32_t cnt) {
    asm volatile("mbarrier.init.shared.b64 [%0], %1;" :: "r"(a), "r"(cnt) : "memory");
}
// store 4B to peer SMEM + count 4 tx bytes on peer's mbarrier, one instruction
__device__ __forceinline__ void st_async_f32(uint32_t a, float v, uint32_t mb) {
    asm volatile("st.async.shared::cluster.mbarrier::complete_tx::bytes.f32 [%0], %1, [%2];"
                 :: "r"(a), "f"(v), "r"(mb) : "memory");
}
__device__ __forceinline__ void mbar_arrive_expect(uint32_t a, uint32_t bytes) {
    asm volatile("mbarrier.arrive.expect_tx.release.cta.shared::cta.b64 _, [%0], %1;"
                 :: "r"(a), "r"(bytes) : "memory");
}
__device__ __forceinline__ void mbar_wait_(uint32_t a, uint32_t par) {
    asm volatile(
        "{\n\t.reg .pred P;\n\t"
        "WL_%=:\n\t"
        "mbarrier.try_wait.parity.acquire.cta.shared::cta.b64 P, [%0], %1, 0x989680;\n\t"
        "@!P bra WL_%=;\n\t}"
        :: "r"(a), "r"(par) : "memory");
}

// ---------------------------------------------------------------------------
// 1) embedding gather
// ---------------------------------------------------------------------------
__global__ void k_embed(const int* __restrict__ wid, const int* __restrict__ tid,
                        const float* __restrict__ wemb, const float* __restrict__ temb) {
    int t = blockIdx.x, k = threadIdx.x;   // <<<512,128>>>
    float v;
    if (k < 100) v = wemb[wid[t] * 100 + k];
    else         v = temb[tid[t] * 28 + (k - 100)];
    g_x[t * H + k] = v;
}

// ---------------------------------------------------------------------------
// 2) fused dual GEMM, 2x2 micro-tile. block (16,16), grid (16,16,2).
// ---------------------------------------------------------------------------
__global__ void __launch_bounds__(256)
k_gemm2(int srcSel, int ldx,
        const float* __restrict__ Wz0, const float* __restrict__ Wz1,
        int woff0, int woff1, int ldw,
        const float* b10, const float* b11,
        const float* b20, const float* b21,
        int dst0, int dst1, int K) {
    const int z = blockIdx.z;
    const float* __restrict__ W  = z ? Wz1 : Wz0;
    const int woff  = z ? woff1 : woff0;
    const float* b1 = z ? b11 : b10;
    const float* b2 = z ? b21 : b20;
    const float* __restrict__ X  = selbuf(srcSel);
    float*       __restrict__ C  = selbuf(z ? dst1 : dst0);

    __shared__ float Xs[32][33];
    __shared__ float Ws[32][33];
    const int tx = threadIdx.x, ty = threadIdx.y;
    const int lid = ty * 16 + tx;
    const int row0 = blockIdx.y * 32, col0 = blockIdx.x * 32;

    float a00 = 0.f, a01 = 0.f, a10 = 0.f, a11 = 0.f;
    for (int k0 = 0; k0 < K; k0 += 32) {
#pragma unroll
        for (int i = 0; i < 4; i++) {
            int e = lid + i * 256, rr = e >> 5, cc = e & 31;
            Xs[rr][cc] = X[(row0 + rr) * ldx + k0 + cc];
            Ws[rr][cc] = W[(col0 + rr) * ldw + woff + k0 + cc];
        }
        __syncthreads();
#pragma unroll
        for (int kk = 0; kk < 32; kk++) {
            float x0 = Xs[2 * ty][kk],  x1 = Xs[2 * ty + 1][kk];
            float w0 = Ws[2 * tx][kk],  w1 = Ws[2 * tx + 1][kk];
            a00 += x0 * w0; a01 += x0 * w1;
            a10 += x1 * w0; a11 += x1 * w1;
        }
        __syncthreads();
    }
    const int r0 = row0 + 2 * ty, c0 = col0 + 2 * tx;
    float bb0 = 0.f, bb1 = 0.f;
    if (b1) { bb0 += b1[c0]; bb1 += b1[c0 + 1]; }
    if (b2) { bb0 += b2[c0]; bb1 += b2[c0 + 1]; }
    C[r0 * 512 + c0]           = a00 + bb0;
    C[r0 * 512 + c0 + 1]       = a01 + bb1;
    C[(r0 + 1) * 512 + c0]     = a10 + bb0;
    C[(r0 + 1) * 512 + c0 + 1] = a11 + bb1;
}

// ---------------------------------------------------------------------------
// 3) LSTM recurrence: grid 4, cluster 2. Blocks {0,1}=fwd, {2,3}=bwd.
//    Rank r owns units [64r,64r+64). lane = 8*slice + ug_in_warp; thread
//    computes all-4-gate partials for its unit over K quarter `slice`.
// ---------------------------------------------------------------------------
__global__ void __launch_bounds__(256, 1) __cluster_dims__(2, 1, 1)
k_recur(int layer, const float* __restrict__ Whh_f, const float* __restrict__ Whh_b,
        const float* __restrict__ h0, const float* __restrict__ c0) {
    const int d = blockIdx.x >> 1;
    const int r = blockIdx.x & 1;
    const int peer = r ^ 1;
    const int t = threadIdx.x;               // 0..255
    const int lane = t & 31, w = t >> 5;
    const int slice = lane >> 3;             // K quarter AND owned gate id
    const int ug = w * 8 + (lane & 7);       // unit local to rank, 0..63
    const int u_glob = r * 64 + ug;          // unit within direction, 0..127

    const float* __restrict__ Whh = d ? Whh_b : Whh_f;
    const float* __restrict__ pre = g_pre[d];
    float* __restrict__ out = layer ? g_h1out : g_h0out;

    __shared__ __align__(16) float h_s[2][H];
    __shared__ __align__(8) unsigned long long mbar;

    const uint32_t mb_a = s2u_(&mbar);
    if (t == 0) mbar_init_(mb_a, 1);         // single elected arrive per phase

    // weights: 4 gate rows of this unit, K columns [32*slice, 32*slice+32)
    unsigned long long wpk[64];              // 4 gates x 16 f32x2
#pragma unroll
    for (int g = 0; g < 4; g++) {
        const float4* Wr = (const float4*)(Whh + (size_t)(g * 128 + u_glob) * H + slice * 32);
#pragma unroll
        for (int k4 = 0; k4 < 8; k4++) {
            float4 v = Wr[k4];
            wpk[g * 16 + 2 * k4]     = pack2_(v.x, v.y);
            wpk[g * 16 + 2 * k4 + 1] = pack2_(v.z, v.w);
        }
    }

    const int row0 = (2 * layer + d) * H;
    if (t < H) h_s[0][t] = h0[row0 + t];
    float c = c0[row0 + u_glob];             // consistent across the 4 slices

    // peer-side addresses (slice0 lanes store my unit's h remotely)
    const uint32_t ph[2] = { mapa_(s2u_(&h_s[0][u_glob]), (uint32_t)peer),
                             mapa_(s2u_(&h_s[1][u_glob]), (uint32_t)peer) };
    const uint32_t pmb   = mapa_(mb_a, (uint32_t)peer);

    __syncthreads();
    asm volatile("barrier.cluster.arrive.aligned;" ::: "memory");
    asm volatile("barrier.cluster.wait.aligned;" ::: "memory");

    const bool isg  = (slice == 2);          // gate 2 = tanh, others sigmoid
    const int  Rj   = slice * 128 + u_glob;  // my gate row in pre[]

    for (int s = 0; s < SEQ; s++) {
        const int ti = d ? (SEQ - 1 - s) : s;
        const float pv = pre[(size_t)ti * G4 + Rj];      // early LDG

        // all-4-gate partials over my K quarter
        const ulonglong2* h2 = (const ulonglong2*)&h_s[s & 1][slice * 32];
        unsigned long long a0 = 0ull, a1 = 0ull, a2 = 0ull, a3 = 0ull;
#pragma unroll
        for (int k = 0; k < 8; k++) {
            ulonglong2 hv = h2[k];
            ffma2_(a0, wpk[0 * 16 + 2 * k], hv.x); ffma2_(a0, wpk[0 * 16 + 2 * k + 1], hv.y);
            ffma2_(a1, wpk[1 * 16 + 2 * k], hv.x); ffma2_(a1, wpk[1 * 16 + 2 * k + 1], hv.y);
            ffma2_(a2, wpk[2 * 16 + 2 * k], hv.x); ffma2_(a2, wpk[2 * 16 + 2 * k + 1], hv.y);
            ffma2_(a3, wpk[3 * 16 + 2 * k], hv.x); ffma2_(a3, wpk[3 * 16 + 2 * k + 1], hv.y);
        }
        float p0 = hsum2_(a0), p1 = hsum2_(a1), p2 = hsum2_(a2), p3 = hsum2_(a3);

        // cross-slice reduction: after 2 rounds every lane holds full sums
        p0 += __shfl_xor_sync(0xffffffffu, p0, 8);
        p1 += __shfl_xor_sync(0xffffffffu, p1, 8);
        p2 += __shfl_xor_sync(0xffffffffu, p2, 8);
        p3 += __shfl_xor_sync(0xffffffffu, p3, 8);
        p0 += __shfl_xor_sync(0xffffffffu, p0, 16);
        p1 += __shfl_xor_sync(0xffffffffu, p1, 16);
        p2 += __shfl_xor_sync(0xffffffffu, p2, 16);
        p3 += __shfl_xor_sync(0xffffffffu, p3, 16);

        // this thread activates gate `slice` only (branchless tanh form)
        float x = (slice == 0 ? p0 : slice == 1 ? p1 : slice == 2 ? p2 : p3) + pv;
        float xx = isg ? x : 0.5f * x;
        float y  = tanh_(xx);
        float a  = isg ? y : 0.5f + 0.5f * y;            // sigmoid via tanh

        // broadcast activations among the 4 slice-threads of this unit
        float b0 = __shfl_xor_sync(0xffffffffu, a, 8);   // gate slice^1
        float c2 = __shfl_xor_sync(0xffffffffu, a, 16);  // gate slice^2
        float d3 = __shfl_xor_sync(0xffffffffu, b0, 16); // gate slice^3
        // v[tt] lives in {a,b0,c2,d3}[slice^tt]
        int s0 = slice;
        float i_ = (s0 == 0) ? a : (s0 == 1) ? b0 : (s0 == 2) ? c2 : d3;
        float f_ = ((s0 ^ 1) == 0) ? a : ((s0 ^ 1) == 1) ? b0 : ((s0 ^ 1) == 2) ? c2 : d3;
        float g_ = ((s0 ^ 2) == 0) ? a : ((s0 ^ 2) == 1) ? b0 : ((s0 ^ 2) == 2) ? c2 : d3;
        float o_ = ((s0 ^ 3) == 0) ? a : ((s0 ^ 3) == 1) ? b0 : ((s0 ^ 3) == 2) ? c2 : d3;

        c = f_ * c + i_ * g_;                // redundant but identical on 4 slices
        float h = o_ * tanh_(c);

        const int nxt = (s + 1) & 1;
        if (slice == 0) {
            h_s[nxt][u_glob] = h;                        // local copy
            out[(size_t)ti * D2 + d * H + u_glob] = h;   // final output
        }
        __syncthreads();                     // locals visible; cur-buffer reads done
        if (slice == 0)
            st_async_f32(ph[nxt], h, pmb);   // peer copy + 4B tx on peer mbar
        if (t == 0)
            mbar_arrive_expect(mb_a, 256);   // expect 64 x 4B from peer
        mbar_wait_(mb_a, s & 1);
    }
}

// ---------------------------------------------------------------------------
// 4) pairwise scorer
// ---------------------------------------------------------------------------
__global__ void k_pairwise(const float* __restrict__ W2, const float* __restrict__ b2) {
    __shared__ float As[32][33];
    __shared__ float Bs[32][33];
    __shared__ float w2s[32];
    int tx = threadIdx.x, ty = threadIdx.y;
    int n = blockIdx.y * 32 + ty;
    int m = blockIdx.x * 32 + tx;
    float acc = 0.0f;
    for (int h0 = 0; h0 < 512; h0 += 32) {
        As[ty][tx] = g_A[n * 512 + h0 + tx];
        Bs[ty][tx] = g_B[(blockIdx.x * 32 + ty) * 512 + h0 + tx];
        if (ty == 0) w2s[tx] = W2[h0 + tx];
        __syncthreads();
#pragma unroll
        for (int hh = 0; hh < 32; hh++) {
            float v = As[ty][hh] + Bs[tx][hh];
            acc += tanh_(v) * w2s[hh];
        }
        __syncthreads();
    }
    float val = acc + b2[0];
    if (n == m) val = 0.0f;
    g_scores[n * 512 + m] = val;
}

// ---------------------------------------------------------------------------
// 5) column sums — coalesced
// ---------------------------------------------------------------------------
__global__ void __launch_bounds__(1024) k_colsum() {
    __shared__ float red[1024];
    const int cc = threadIdx.x & 63;
    const int rg = threadIdx.x >> 6;
    const int c  = blockIdx.x * 64 + cc;
    float s = 0.0f;
    for (int n = rg; n < SEQ; n += 16)
        s += g_scores[n * 512 + c];
    red[threadIdx.x] = s;
    __syncthreads();
    for (int off = 512; off >= 64; off >>= 1) {
        if (threadIdx.x < off) red[threadIdx.x] += red[threadIdx.x + off];
        __syncthreads();
    }
    if (threadIdx.x < 64) g_colsum[c] = red[threadIdx.x];
}

// ---------------------------------------------------------------------------
// 6) normalize + row softmax (shuffle reductions)
// ---------------------------------------------------------------------------
__global__ void __launch_bounds__(512) k_softmax(float* __restrict__ out) {
    __shared__ float sred[16];
    const int n = blockIdx.x, m = threadIdx.x;
    const int lane = m & 31, wid = m >> 5;
    float v = g_scores[n * 512 + m] / g_colsum[m];

    float wm = v;
#pragma unroll
    for (int off = 16; off > 0; off >>= 1)
        wm = fmaxf(wm, __shfl_xor_sync(0xffffffffu, wm, off));
    if (lane == 0) sred[wid] = wm;
    __syncthreads();
    if (wid == 0) {
        float x = sred[lane & 15];
#pragma unroll
        for (int off = 8; off > 0; off >>= 1)
            x = fmaxf(x, __shfl_xor_sync(0xffffffffu, x, off));
        if (lane == 0) sred[0] = x;
    }
    __syncthreads();
    const float mx = sred[0];
    __syncthreads();

    float p = __expf(v - mx);
    float ws = p;
#pragma unroll
    for (int off = 16; off > 0; off >>= 1)
        ws += __shfl_xor_sync(0xffffffffu, ws, off);
    if (lane == 0) sred[wid] = ws;
    __syncthreads();
    if (wid == 0) {
        float x = sred[lane & 15];
#pragma unroll
        for (int off = 8; off > 0; off >>= 1)
            x += __shfl_xor_sync(0xffffffffu, x, off);
        if (lane == 0) sred[0] = x;
    }
    __syncthreads();
    out[n * 512 + m] = p / sred[0];
}

// ---------------------------------------------------------------------------
// launch — ONLY kernel launches.
// ---------------------------------------------------------------------------
extern "C" void kernel_launch(void* const* d_in, const int* in_sizes, int n_in,
                              void* d_out, int out_size) {
    const int*   word_ids = (const int*)d_in[0];
    const int*   tag_ids  = (const int*)d_in[1];
    const float* wemb     = (const float*)d_in[2];
    const float* temb     = (const float*)d_in[3];
    const float* h0       = (const float*)d_in[4];
    const float* c0       = (const float*)d_in[5];
    const float* Wih_l0f  = (const float*)d_in[6];
    const float* Whh_l0f  = (const float*)d_in[7];
    const float* bih_l0f  = (const float*)d_in[8];
    const float* bhh_l0f  = (const float*)d_in[9];
    const float* Wih_l0b  = (const float*)d_in[10];
    const float* Whh_l0b  = (const float*)d_in[11];
    const float* bih_l0b  = (const float*)d_in[12];
    const float* bhh_l0b  = (const float*)d_in[13];
    const float* Wih_l1f  = (const float*)d_in[14];
    const float* Whh_l1f  = (const float*)d_in[15];
    const float* bih_l1f  = (const float*)d_in[16];
    const float* bhh_l1f  = (const float*)d_in[17];
    const float* Wih_l1b  = (const float*)d_in[18];
    const float* Whh_l1b  = (const float*)d_in[19];
    const float* bih_l1b  = (const float*)d_in[20];
    const float* bhh_l1b  = (const float*)d_in[21];
    const float* W1       = (const float*)d_in[22];
    const float* b1       = (const float*)d_in[23];
    const float* W2       = (const float*)d_in[24];
    const float* b2       = (const float*)d_in[25];
    float* out = (float*)d_out;

    dim3 gblk(16, 16);
    dim3 ggrd2(16, 16, 2);
    const float* nul = (const float*)0;

    k_embed<<<512, 128>>>(word_ids, tag_ids, wemb, temb);

    // layer 0
    k_gemm2<<<ggrd2, gblk>>>(BUF_X, H, Wih_l0f, Wih_l0b, 0, 0, 128,
                             bih_l0f, bih_l0b, bhh_l0f, bhh_l0b,
                             BUF_PREF, BUF_PREB, H);
    k_recur<<<4, 256>>>(0, Whh_l0f, Whh_l0b, h0, c0);

    // layer 1
    k_gemm2<<<ggrd2, gblk>>>(BUF_H0OUT, D2, Wih_l1f, Wih_l1b, 0, 0, 256,
                             bih_l1f, bih_l1b, bhh_l1f, bhh_l1b,
                             BUF_PREF, BUF_PREB, D2);
    k_recur<<<4, 256>>>(1, Whh_l1f, Whh_l1b, h0, c0);

    // MLP projections: A = h@W1[:, :256].T + b1 ; B = h@W1[:, 256:].T
    k_gemm2<<<ggrd2, gblk>>>(BUF_H1OUT, D2, W1, W1, 0, 256, 512,
                             b1, nul, nul, nul,
                             BUF_A, BUF_B, D2);

    k_pairwise<<<dim3(16, 16), dim3(32, 32)>>>(W2, b2);
    k_colsum<<<8, 1024>>>();
    k_softmax<<<512, 512>>>(out);
}

// round 9
// speedup vs baseline: 10.4611x; 1.0678x over previous
#include <cuda_runtime.h>
#include <cuda_bf16.h>
#include <cstdint>

// ---------------------------------------------------------------------------
// DependencyParseModel: 2-layer BiLSTM (SEQ=512, H=128) -> pairwise tanh MLP
// scorer (512^3) -> column normalize -> row softmax.
//
// Round 9 == Round 8 resubmission (R8 never ran: device busy at init).
// Recurrence:
//   - h exchange via ONE cp.async.bulk (256B DSMEM copy, single complete_tx)
//     instead of 64 individually-signalled st.async ops.
//   - mid-step mbarrier wait: local-K-half FFMAs run BEFORE the wait,
//     hiding the DSMEM hop; remote-K-half after.
// ---------------------------------------------------------------------------

#define SEQ 512
#define H   128
#define G4  512      // 4*H gates
#define D2  256      // 2*H concat

// ---- device scratch ----
__device__ float g_x[SEQ * H];
__device__ float g_pre[2][SEQ * G4];
__device__ float g_h0out[SEQ * D2];
__device__ float g_h1out[SEQ * D2];
__device__ float g_A[SEQ * 512];
__device__ float g_B[SEQ * 512];
__device__ float g_scores[SEQ * SEQ];
__device__ float g_colsum[SEQ];

#define BUF_X     0
#define BUF_PREF  1
#define BUF_PREB  2
#define BUF_H0OUT 3
#define BUF_H1OUT 4
#define BUF_A     5
#define BUF_B     6

__device__ __forceinline__ float* selbuf(int s) {
    switch (s) {
        case BUF_X:     return g_x;
        case BUF_PREF:  return g_pre[0];
        case BUF_PREB:  return g_pre[1];
        case BUF_H0OUT: return g_h0out;
        case BUF_H1OUT: return g_h1out;
        case BUF_A:     return g_A;
        default:        return g_B;
    }
}

// ---- math helpers ----
__device__ __forceinline__ float tanh_(float x) {
    float ax = fabsf(x);
    float e  = __expf(-2.0f * ax);
    float r  = __fdividef(1.0f - e, 1.0f + e);
    return __int_as_float(__float_as_int(r) | (__float_as_int(x) & 0x80000000));
}

// ---- packed f32x2 helpers ----
__device__ __forceinline__ unsigned long long pack2_(float lo, float hi) {
    unsigned long long r;
    asm("mov.b64 %0, {%1, %2};" : "=l"(r) : "f"(lo), "f"(hi));
    return r;
}
__device__ __forceinline__ void ffma2_(unsigned long long& acc,
                                       unsigned long long a, unsigned long long b) {
    asm("fma.rn.f32x2 %0, %1, %2, %0;" : "+l"(acc) : "l"(a), "l"(b));
}
__device__ __forceinline__ float hsum2_(unsigned long long v) {
    float lo, hi;
    asm("mov.b64 {%0, %1}, %2;" : "=f"(lo), "=f"(hi) : "l"(v));
    return lo + hi;
}

// ---- cluster / mbarrier helpers ----
__device__ __forceinline__ uint32_t s2u_(const void* p) {
    uint32_t a;
    asm("{ .reg .u64 t; cvta.to.shared.u64 t, %1; cvt.u32.u64 %0, t; }"
        : "=r"(a) : "l"(p));
    return a;
}
__device__ __forceinline__ uint32_t mapa_(uint32_t a, uint32_t rank) {
    uint32_t o;
    asm("mapa.shared::cluster.u32 %0, %1, %2;" : "=r"(o) : "r"(a), "r"(rank));
    return o;
}
__device__ __forceinline__ void mbar_init_(uint32_t a, uint32_t cnt) {
    asm volatile("mbarrier.init.shared.b64 [%0], %1;" :: "r"(a), "r"(cnt) : "memory");
}
__device__ __forceinline__ void mbar_arrive_plain(uint32_t a) {
    asm volatile("mbarrier.arrive.release.cta.shared::cta.b64 _, [%0];"
                 :: "r"(a) : "memory");
}
__device__ __forceinline__ void mbar_arrive_expect(uint32_t a, uint32_t bytes) {
    asm volatile("mbarrier.arrive.expect_tx.release.cta.shared::cta.b64 _, [%0], %1;"
                 :: "r"(a), "r"(bytes) : "memory");
}
__device__ __forceinline__ void mbar_wait_(uint32_t a, uint32_t par) {
    asm volatile(
        "{\n\t.reg .pred P;\n\t"
        "WL_%=:\n\t"
        "mbarrier.try_wait.parity.acquire.cta.shared::cta.b64 P, [%0], %1, 0x989680;\n\t"
        "@!P bra WL_%=;\n\t}"
        :: "r"(a), "r"(par) : "memory");
}
// 256B SMEM->peer-SMEM bulk copy, completing 256B tx on the PEER's mbarrier
__device__ __forceinline__ void bulk_to_peer(uint32_t dst, uint32_t src,
                                             uint32_t bytes, uint32_t peer_mb) {
    asm volatile(
        "cp.async.bulk.shared::cluster.shared::cta.mbarrier::complete_tx::bytes "
        "[%0], [%1], %2, [%3];"
        :: "r"(dst), "r"(src), "r"(bytes), "r"(peer_mb) : "memory");
}
__device__ __forceinline__ void fence_async_() {
    asm volatile("fence.proxy.async.shared::cta;" ::: "memory");
}

// ---------------------------------------------------------------------------
// 1) embedding gather
// ---------------------------------------------------------------------------
__global__ void k_embed(const int* __restrict__ wid, const int* __restrict__ tid,
                        const float* __restrict__ wemb, const float* __restrict__ temb) {
    int t = blockIdx.x, k = threadIdx.x;   // <<<512,128>>>
    float v;
    if (k < 100) v = wemb[wid[t] * 100 + k];
    else         v = temb[tid[t] * 28 + (k - 100)];
    g_x[t * H + k] = v;
}

// ---------------------------------------------------------------------------
// 2) fused dual GEMM, 2x2 micro-tile. block (16,16), grid (16,16,2).
// ---------------------------------------------------------------------------
__global__ void __launch_bounds__(256)
k_gemm2(int srcSel, int ldx,
        const float* __restrict__ Wz0, const float* __restrict__ Wz1,
        int woff0, int woff1, int ldw,
        const float* b10, const float* b11,
        const float* b20, const float* b21,
        int dst0, int dst1, int K) {
    const int z = blockIdx.z;
    const float* __restrict__ W  = z ? Wz1 : Wz0;
    const int woff  = z ? woff1 : woff0;
    const float* b1 = z ? b11 : b10;
    const float* b2 = z ? b21 : b20;
    const float* __restrict__ X  = selbuf(srcSel);
    float*       __restrict__ C  = selbuf(z ? dst1 : dst0);

    __shared__ float Xs[32][33];
    __shared__ float Ws[32][33];
    const int tx = threadIdx.x, ty = threadIdx.y;
    const int lid = ty * 16 + tx;
    const int row0 = blockIdx.y * 32, col0 = blockIdx.x * 32;

    float a00 = 0.f, a01 = 0.f, a10 = 0.f, a11 = 0.f;
    for (int k0 = 0; k0 < K; k0 += 32) {
#pragma unroll
        for (int i = 0; i < 4; i++) {
            int e = lid + i * 256, rr = e >> 5, cc = e & 31;
            Xs[rr][cc] = X[(row0 + rr) * ldx + k0 + cc];
            Ws[rr][cc] = W[(col0 + rr) * ldw + woff + k0 + cc];
        }
        __syncthreads();
#pragma unroll
        for (int kk = 0; kk < 32; kk++) {
            float x0 = Xs[2 * ty][kk],  x1 = Xs[2 * ty + 1][kk];
            float w0 = Ws[2 * tx][kk],  w1 = Ws[2 * tx + 1][kk];
            a00 += x0 * w0; a01 += x0 * w1;
            a10 += x1 * w0; a11 += x1 * w1;
        }
        __syncthreads();
    }
    const int r0 = row0 + 2 * ty, c0 = col0 + 2 * tx;
    float bb0 = 0.f, bb1 = 0.f;
    if (b1) { bb0 += b1[c0]; bb1 += b1[c0 + 1]; }
    if (b2) { bb0 += b2[c0]; bb1 += b2[c0 + 1]; }
    C[r0 * 512 + c0]           = a00 + bb0;
    C[r0 * 512 + c0 + 1]       = a01 + bb1;
    C[(r0 + 1) * 512 + c0]     = a10 + bb0;
    C[(r0 + 1) * 512 + c0 + 1] = a11 + bb1;
}

// ---------------------------------------------------------------------------
// 3) LSTM recurrence: grid 4, cluster 2. Blocks {0,1}=fwd, {2,3}=bwd.
//    Rank r owns units [64r,64r+64). Thread covers all 4 gates of unit
//    u = r*64 + w*8 + (lane&7) over K = {local 16 + remote 16} per slice.
//    Per step: local-half FFMAs -> mbar wait (peer bulk) -> remote-half
//    FFMAs -> shfl reduce -> activations -> one 256B bulk copy to peer.
// ---------------------------------------------------------------------------
__global__ void __launch_bounds__(256, 1) __cluster_dims__(2, 1, 1)
k_recur(int layer, const float* __restrict__ Whh_f, const float* __restrict__ Whh_b,
        const float* __restrict__ h0, const float* __restrict__ c0) {
    const int d = blockIdx.x >> 1;
    const int r = blockIdx.x & 1;
    const int peer = r ^ 1;
    const int t = threadIdx.x;               // 0..255
    const int lane = t & 31, w = t >> 5;
    const int slice = lane >> 3;             // 16-wide K sub-slice AND gate id
    const int ug = w * 8 + (lane & 7);       // unit local to rank, 0..63
    const int u_glob = r * 64 + ug;          // unit within direction, 0..127

    const float* __restrict__ Whh = d ? Whh_b : Whh_f;
    const float* __restrict__ pre = g_pre[d];
    float* __restrict__ out = layer ? g_h1out : g_h0out;

    __shared__ __align__(16) float h_s[2][H];
    __shared__ __align__(8) unsigned long long mbar;

    const uint32_t mb_a = s2u_(&mbar);
    if (t == 0) mbar_init_(mb_a, 1);

    const int kloc = r * 64 + 16 * slice;    // local-half K base (own units)
    const int krem = peer * 64 + 16 * slice; // remote-half K base (peer units)

    // weights: 4 gates x (16 local + 16 remote) K as f32x2
    unsigned long long wl[32], wr[32];
#pragma unroll
    for (int g = 0; g < 4; g++) {
        const float4* Wl = (const float4*)(Whh + (size_t)(g * 128 + u_glob) * H + kloc);
        const float4* Wm = (const float4*)(Whh + (size_t)(g * 128 + u_glob) * H + krem);
#pragma unroll
        for (int k4 = 0; k4 < 4; k4++) {
            float4 v = Wl[k4];
            wl[g * 8 + 2 * k4]     = pack2_(v.x, v.y);
            wl[g * 8 + 2 * k4 + 1] = pack2_(v.z, v.w);
            float4 u = Wm[k4];
            wr[g * 8 + 2 * k4]     = pack2_(u.x, u.y);
            wr[g * 8 + 2 * k4 + 1] = pack2_(u.z, u.w);
        }
    }

    const int row0 = (2 * layer + d) * H;
    if (t < H) h_s[0][t] = h0[row0 + t];
    float c = c0[row0 + u_glob];             // same across the 4 slice-threads

    // bulk copy endpoints: own contiguous 64-unit block of each buffer
    const uint32_t src_blk[2] = { s2u_(&h_s[0][r * 64]), s2u_(&h_s[1][r * 64]) };
    const uint32_t dst_blk[2] = { mapa_(src_blk[0], (uint32_t)peer),
                                  mapa_(src_blk[1], (uint32_t)peer) };
    const uint32_t pmb = mapa_(mb_a, (uint32_t)peer);

    __syncthreads();
    asm volatile("barrier.cluster.arrive.aligned;" ::: "memory");
    asm volatile("barrier.cluster.wait.aligned;" ::: "memory");
    if (t == 0) mbar_arrive_plain(mb_a);     // self-complete phase 0 (step 0 needs no peer data)

    const bool isg = (slice == 2);           // gate 2 = tanh, others sigmoid
    const int  Rj  = slice * 128 + u_glob;   // my gate row in pre[]

    for (int s = 0; s < SEQ; s++) {
        const int ti = d ? (SEQ - 1 - s) : s;
        const float pv = pre[(size_t)ti * G4 + Rj];      // early LDG
        const int cur = s & 1;

        // ---- phase A: local K half (own h, no peer dependency) ----
        const ulonglong2* hl = (const ulonglong2*)&h_s[cur][kloc];
        unsigned long long a0 = 0ull, a1 = 0ull, a2 = 0ull, a3 = 0ull;
#pragma unroll
        for (int k = 0; k < 4; k++) {
            ulonglong2 hv = hl[k];
            ffma2_(a0, wl[0 * 8 + 2 * k], hv.x); ffma2_(a0, wl[0 * 8 + 2 * k + 1], hv.y);
            ffma2_(a1, wl[1 * 8 + 2 * k], hv.x); ffma2_(a1, wl[1 * 8 + 2 * k + 1], hv.y);
            ffma2_(a2, wl[2 * 8 + 2 * k], hv.x); ffma2_(a2, wl[2 * 8 + 2 * k + 1], hv.y);
            ffma2_(a3, wl[3 * 8 + 2 * k], hv.x); ffma2_(a3, wl[3 * 8 + 2 * k + 1], hv.y);
        }

        // ---- wait for peer's 256B bulk into h_s[cur][peer range] ----
        mbar_wait_(mb_a, cur);

        // ---- phase B: remote K half ----
        const ulonglong2* hr = (const ulonglong2*)&h_s[cur][krem];
#pragma unroll
        for (int k = 0; k < 4; k++) {
            ulonglong2 hv = hr[k];
            ffma2_(a0, wr[0 * 8 + 2 * k], hv.x); ffma2_(a0, wr[0 * 8 + 2 * k + 1], hv.y);
            ffma2_(a1, wr[1 * 8 + 2 * k], hv.x); ffma2_(a1, wr[1 * 8 + 2 * k + 1], hv.y);
            ffma2_(a2, wr[2 * 8 + 2 * k], hv.x); ffma2_(a2, wr[2 * 8 + 2 * k + 1], hv.y);
            ffma2_(a3, wr[3 * 8 + 2 * k], hv.x); ffma2_(a3, wr[3 * 8 + 2 * k + 1], hv.y);
        }
        float p0 = hsum2_(a0), p1 = hsum2_(a1), p2 = hsum2_(a2), p3 = hsum2_(a3);

        // cross-slice reduction: after 2 rounds every lane holds full sums
        p0 += __shfl_xor_sync(0xffffffffu, p0, 8);
        p1 += __shfl_xor_sync(0xffffffffu, p1, 8);
        p2 += __shfl_xor_sync(0xffffffffu, p2, 8);
        p3 += __shfl_xor_sync(0xffffffffu, p3, 8);
        p0 += __shfl_xor_sync(0xffffffffu, p0, 16);
        p1 += __shfl_xor_sync(0xffffffffu, p1, 16);
        p2 += __shfl_xor_sync(0xffffffffu, p2, 16);
        p3 += __shfl_xor_sync(0xffffffffu, p3, 16);

        // activate gate `slice` only (sigmoid via tanh, branchless)
        float x = (slice == 0 ? p0 : slice == 1 ? p1 : slice == 2 ? p2 : p3) + pv;
        float xx = isg ? x : 0.5f * x;
        float y  = tanh_(xx);
        float a  = isg ? y : 0.5f + 0.5f * y;

        // exchange activations among the 4 slice-threads of this unit
        float b0 = __shfl_xor_sync(0xffffffffu, a, 8);
        float c2 = __shfl_xor_sync(0xffffffffu, a, 16);
        float d3 = __shfl_xor_sync(0xffffffffu, b0, 16);
        int s0 = slice;
        float i_ = (s0 == 0) ? a : (s0 == 1) ? b0 : (s0 == 2) ? c2 : d3;
        float f_ = ((s0 ^ 1) == 0) ? a : ((s0 ^ 1) == 1) ? b0 : ((s0 ^ 1) == 2) ? c2 : d3;
        float g_ = ((s0 ^ 2) == 0) ? a : ((s0 ^ 2) == 1) ? b0 : ((s0 ^ 2) == 2) ? c2 : d3;
        float o_ = ((s0 ^ 3) == 0) ? a : ((s0 ^ 3) == 1) ? b0 : ((s0 ^ 3) == 2) ? c2 : d3;

        c = f_ * c + i_ * g_;                // redundant but identical on 4 slices
        float h = o_ * tanh_(c);

        const int nxt = cur ^ 1;
        if (slice == 0) {
            h_s[nxt][u_glob] = h;                        // local copy
            out[(size_t)ti * D2 + d * H + u_glob] = h;   // final output
        }
        __syncthreads();                     // local h writes visible
        if (t == 0 && s + 1 < SEQ) {
            fence_async_();                  // generic->async proxy ordering
            bulk_to_peer(dst_blk[nxt], src_blk[nxt], 256u, pmb);
            mbar_arrive_expect(mb_a, 256);   // arm phase s+1 (arrive + expect 256B)
        }
    }
}

// ---------------------------------------------------------------------------
// 4) pairwise scorer
// ---------------------------------------------------------------------------
__global__ void k_pairwise(const float* __restrict__ W2, const float* __restrict__ b2) {
    __shared__ float As[32][33];
    __shared__ float Bs[32][33];
    __shared__ float w2s[32];
    int tx = threadIdx.x, ty = threadIdx.y;
    int n = blockIdx.y * 32 + ty;
    int m = blockIdx.x * 32 + tx;
    float acc = 0.0f;
    for (int h0 = 0; h0 < 512; h0 += 32) {
        As[ty][tx] = g_A[n * 512 + h0 + tx];
        Bs[ty][tx] = g_B[(blockIdx.x * 32 + ty) * 512 + h0 + tx];
        if (ty == 0) w2s[tx] = W2[h0 + tx];
        __syncthreads();
#pragma unroll
        for (int hh = 0; hh < 32; hh++) {
            float v = As[ty][hh] + Bs[tx][hh];
            acc += tanh_(v) * w2s[hh];
        }
        __syncthreads();
    }
    float val = acc + b2[0];
    if (n == m) val = 0.0f;
    g_scores[n * 512 + m] = val;
}

// ---------------------------------------------------------------------------
// 5) column sums — coalesced
// ---------------------------------------------------------------------------
__global__ void __launch_bounds__(1024) k_colsum() {
    __shared__ float red[1024];
    const int cc = threadIdx.x & 63;
    const int rg = threadIdx.x >> 6;
    const int c  = blockIdx.x * 64 + cc;
    float s = 0.0f;
    for (int n = rg; n < SEQ; n += 16)
        s += g_scores[n * 512 + c];
    red[threadIdx.x] = s;
    __syncthreads();
    for (int off = 512; off >= 64; off >>= 1) {
        if (threadIdx.x < off) red[threadIdx.x] += red[threadIdx.x + off];
        __syncthreads();
    }
    if (threadIdx.x < 64) g_colsum[c] = red[threadIdx.x];
}

// ---------------------------------------------------------------------------
// 6) normalize + row softmax (shuffle reductions)
// ---------------------------------------------------------------------------
__global__ void __launch_bounds__(512) k_softmax(float* __restrict__ out) {
    __shared__ float sred[16];
    const int n = blockIdx.x, m = threadIdx.x;
    const int lane = m & 31, wid = m >> 5;
    float v = g_scores[n * 512 + m] / g_colsum[m];

    float wm = v;
#pragma unroll
    for (int off = 16; off > 0; off >>= 1)
        wm = fmaxf(wm, __shfl_xor_sync(0xffffffffu, wm, off));
    if (lane == 0) sred[wid] = wm;
    __syncthreads();
    if (wid == 0) {
        float x = sred[lane & 15];
#pragma unroll
        for (int off = 8; off > 0; off >>= 1)
            x = fmaxf(x, __shfl_xor_sync(0xffffffffu, x, off));
        if (lane == 0) sred[0] = x;
    }
    __syncthreads();
    const float mx = sred[0];
    __syncthreads();

    float p = __expf(v - mx);
    float ws = p;
#pragma unroll
    for (int off = 16; off > 0; off >>= 1)
        ws += __shfl_xor_sync(0xffffffffu, ws, off);
    if (lane == 0) sred[wid] = ws;
    __syncthreads();
    if (wid == 0) {
        float x = sred[lane & 15];
#pragma unroll
        for (int off = 8; off > 0; off >>= 1)
            x += __shfl_xor_sync(0xffffffffu, x, off);
        if (lane == 0) sred[0] = x;
    }
    __syncthreads();
    out[n * 512 + m] = p / sred[0];
}

// ---------------------------------------------------------------------------
// launch — ONLY kernel launches.
// ---------------------------------------------------------------------------
extern "C" void kernel_launch(void* const* d_in, const int* in_sizes, int n_in,
                              void* d_out, int out_size) {
    const int*   word_ids = (const int*)d_in[0];
    const int*   tag_ids  = (const int*)d_in[1];
    const float* wemb     = (const float*)d_in[2];
    const float* temb     = (const float*)d_in[3];
    const float* h0       = (const float*)d_in[4];
    const float* c0       = (const float*)d_in[5];
    const float* Wih_l0f  = (const float*)d_in[6];
    const float* Whh_l0f  = (const float*)d_in[7];
    const float* bih_l0f  = (const float*)d_in[8];
    const float* bhh_l0f  = (const float*)d_in[9];
    const float* Wih_l0b  = (const float*)d_in[10];
    const float* Whh_l0b  = (const float*)d_in[11];
    const float* bih_l0b  = (const float*)d_in[12];
    const float* bhh_l0b  = (const float*)d_in[13];
    const float* Wih_l1f  = (const float*)d_in[14];
    const float* Whh_l1f  = (const float*)d_in[15];
    const float* bih_l1f  = (const float*)d_in[16];
    const float* bhh_l1f  = (const float*)d_in[17];
    const float* Wih_l1b  = (const float*)d_in[18];
    const float* Whh_l1b  = (const float*)d_in[19];
    const float* bih_l1b  = (const float*)d_in[20];
    const float* bhh_l1b  = (const float*)d_in[21];
    const float* W1       = (const float*)d_in[22];
    const float* b1       = (const float*)d_in[23];
    const float* W2       = (const float*)d_in[24];
    const float* b2       = (const float*)d_in[25];
    float* out = (float*)d_out;

    dim3 gblk(16, 16);
    dim3 ggrd2(16, 16, 2);
    const float* nul = (const float*)0;

    k_embed<<<512, 128>>>(word_ids, tag_ids, wemb, temb);

    // layer 0
    k_gemm2<<<ggrd2, gblk>>>(BUF_X, H, Wih_l0f, Wih_l0b, 0, 0, 128,
                             bih_l0f, bih_l0b, bhh_l0f, bhh_l0b,
                             BUF_PREF, BUF_PREB, H);
    k_recur<<<4, 256>>>(0, Whh_l0f, Whh_l0b, h0, c0);

    // layer 1
    k_gemm2<<<ggrd2, gblk>>>(BUF_H0OUT, D2, Wih_l1f, Wih_l1b, 0, 0, 256,
                             bih_l1f, bih_l1b, bhh_l1f, bhh_l1b,
                             BUF_PREF, BUF_PREB, D2);
    k_recur<<<4, 256>>>(1, Whh_l1f, Whh_l1b, h0, c0);

    // MLP projections: A = h@W1[:, :256].T + b1 ; B = h@W1[:, 256:].T
    k_gemm2<<<ggrd2, gblk>>>(BUF_H1OUT, D2, W1, W1, 0, 256, 512,
                             b1, nul, nul, nul,
                             BUF_A, BUF_B, D2);

    k_pairwise<<<dim3(16, 16), dim3(32, 32)>>>(W2, b2);
    k_colsum<<<8, 1024>>>();
    k_softmax<<<512, 512>>>(out);
}

// round 12
// speedup vs baseline: 11.0217x; 1.0536x over previous
#include <cuda_runtime.h>
#include <cuda_bf16.h>
#include <cstdint>

// ---------------------------------------------------------------------------
// DependencyParseModel: 2-layer BiLSTM (SEQ=512, H=128) -> pairwise tanh MLP
// scorer (512^3) -> column normalize -> row softmax.
//
// Round 12 (R10/R11 content, never executed due to broker timeouts, plus
// one new fix):
//   - recur: 3-shfl tailored gate reduction + 3 independent bcast shfls,
//     and NEW: one-step-ahead prefetch of the pre[] LDG so its L2 latency
//     is fully hidden under the previous step's compute.
//   - gemm: 4x4 micro-tile (64x64 block), k-major SMEM, float4 LDS.
//   - dummy k_embed re-launch so ncu (-s 5 -c 1) captures k_recur.
// ---------------------------------------------------------------------------

#define SEQ 512
#define H   128
#define G4  512      // 4*H gates
#define D2  256      // 2*H concat

// ---- device scratch ----
__device__ float g_x[SEQ * H];
__device__ float g_pre[2][SEQ * G4];
__device__ float g_h0out[SEQ * D2];
__device__ float g_h1out[SEQ * D2];
__device__ float g_A[SEQ * 512];
__device__ float g_B[SEQ * 512];
__device__ float g_scores[SEQ * SEQ];
__device__ float g_colsum[SEQ];

#define BUF_X     0
#define BUF_PREF  1
#define BUF_PREB  2
#define BUF_H0OUT 3
#define BUF_H1OUT 4
#define BUF_A     5
#define BUF_B     6

__device__ __forceinline__ float* selbuf(int s) {
    switch (s) {
        case BUF_X:     return g_x;
        case BUF_PREF:  return g_pre[0];
        case BUF_PREB:  return g_pre[1];
        case BUF_H0OUT: return g_h0out;
        case BUF_H1OUT: return g_h1out;
        case BUF_A:     return g_A;
        default:        return g_B;
    }
}

// ---- math helpers ----
__device__ __forceinline__ float tanh_(float x) {
    float ax = fabsf(x);
    float e  = __expf(-2.0f * ax);
    float r  = __fdividef(1.0f - e, 1.0f + e);
    return __int_as_float(__float_as_int(r) | (__float_as_int(x) & 0x80000000));
}

// ---- packed f32x2 helpers ----
__device__ __forceinline__ unsigned long long pack2_(float lo, float hi) {
    unsigned long long r;
    asm("mov.b64 %0, {%1, %2};" : "=l"(r) : "f"(lo), "f"(hi));
    return r;
}
__device__ __forceinline__ void ffma2_(unsigned long long& acc,
                                       unsigned long long a, unsigned long long b) {
    asm("fma.rn.f32x2 %0, %1, %2, %0;" : "+l"(acc) : "l"(a), "l"(b));
}
__device__ __forceinline__ float hsum2_(unsigned long long v) {
    float lo, hi;
    asm("mov.b64 {%0, %1}, %2;" : "=f"(lo), "=f"(hi) : "l"(v));
    return lo + hi;
}

// ---- cluster / mbarrier helpers ----
__device__ __forceinline__ uint32_t s2u_(const void* p) {
    uint32_t a;
    asm("{ .reg .u64 t; cvta.to.shared.u64 t, %1; cvt.u32.u64 %0, t; }"
        : "=r"(a) : "l"(p));
    return a;
}
__device__ __forceinline__ uint32_t mapa_(uint32_t a, uint32_t rank) {
    uint32_t o;
    asm("mapa.shared::cluster.u32 %0, %1, %2;" : "=r"(o) : "r"(a), "r"(rank));
    return o;
}
__device__ __forceinline__ void mbar_init_(uint32_t a, uint32_t cnt) {
    asm volatile("mbarrier.init.shared.b64 [%0], %1;" :: "r"(a), "r"(cnt) : "memory");
}
__device__ __forceinline__ void mbar_arrive_plain(uint32_t a) {
    asm volatile("mbarrier.arrive.release.cta.shared::cta.b64 _, [%0];"
                 :: "r"(a) : "memory");
}
__device__ __forceinline__ void mbar_arrive_expect(uint32_t a, uint32_t bytes) {
    asm volatile("mbarrier.arrive.expect_tx.release.cta.shared::cta.b64 _, [%0], %1;"
                 :: "r"(a), "r"(bytes) : "memory");
}
__device__ __forceinline__ void mbar_wait_(uint32_t a, uint32_t par) {
    asm volatile(
        "{\n\t.reg .pred P;\n\t"
        "WL_%=:\n\t"
        "mbarrier.try_wait.parity.acquire.cta.shared::cta.b64 P, [%0], %1, 0x989680;\n\t"
        "@!P bra WL_%=;\n\t}"
        :: "r"(a), "r"(par) : "memory");
}
__device__ __forceinline__ void bulk_to_peer(uint32_t dst, uint32_t src,
                                             uint32_t bytes, uint32_t peer_mb) {
    asm volatile(
        "cp.async.bulk.shared::cluster.shared::cta.mbarrier::complete_tx::bytes "
        "[%0], [%1], %2, [%3];"
        :: "r"(dst), "r"(src), "r"(bytes), "r"(peer_mb) : "memory");
}
__device__ __forceinline__ void fence_async_() {
    asm volatile("fence.proxy.async.shared::cta;" ::: "memory");
}

// ---------------------------------------------------------------------------
// 1) embedding gather (idempotent — also the ncu launch-order spacer)
// ---------------------------------------------------------------------------
__global__ void k_embed(const int* __restrict__ wid, const int* __restrict__ tid,
                        const float* __restrict__ wemb, const float* __restrict__ temb) {
    int t = blockIdx.x, k = threadIdx.x;   // <<<512,128>>>
    float v;
    if (k < 100) v = wemb[wid[t] * 100 + k];
    else         v = temb[tid[t] * 28 + (k - 100)];
    g_x[t * H + k] = v;
}

// ---------------------------------------------------------------------------
// 2) fused dual GEMM, 4x4 micro-tile. block (16,16), grid (8,8,2).
// ---------------------------------------------------------------------------
__global__ void __launch_bounds__(256)
k_gemm4(int srcSel, int ldx,
        const float* __restrict__ Wz0, const float* __restrict__ Wz1,
        int woff0, int woff1, int ldw,
        const float* b10, const float* b11,
        const float* b20, const float* b21,
        int dst0, int dst1, int K) {
    const int z = blockIdx.z;
    const float* __restrict__ W  = z ? Wz1 : Wz0;
    const int woff  = z ? woff1 : woff0;
    const float* b1 = z ? b11 : b10;
    const float* b2 = z ? b21 : b20;
    const float* __restrict__ X  = selbuf(srcSel);
    float*       __restrict__ C  = selbuf(z ? dst1 : dst0);

    __shared__ __align__(16) float Xs[32][68];   // [kk][row], 272B row stride
    __shared__ __align__(16) float Ws[32][68];
    const int tx = threadIdx.x, ty = threadIdx.y;    // (16,16)
    const int lid = ty * 16 + tx;                    // 0..255
    const int row0 = blockIdx.y * 64, col0 = blockIdx.x * 64;

    float acc[4][4] = {};
    for (int k0 = 0; k0 < K; k0 += 32) {
#pragma unroll
        for (int i = 0; i < 8; i++) {
            int e  = lid + i * 256;                  // 0..2047
            int cc = e & 31, rr = e >> 5;            // coalesced LDG
            Xs[cc][rr] = X[(row0 + rr) * ldx + k0 + cc];
            Ws[cc][rr] = W[(col0 + rr) * ldw + woff + k0 + cc];
        }
        __syncthreads();
#pragma unroll
        for (int kk = 0; kk < 32; kk++) {
            float4 xv = *(const float4*)&Xs[kk][4 * ty];
            float4 wv = *(const float4*)&Ws[kk][4 * tx];
            acc[0][0] += xv.x * wv.x; acc[0][1] += xv.x * wv.y;
            acc[0][2] += xv.x * wv.z; acc[0][3] += xv.x * wv.w;
            acc[1][0] += xv.y * wv.x; acc[1][1] += xv.y * wv.y;
            acc[1][2] += xv.y * wv.z; acc[1][3] += xv.y * wv.w;
            acc[2][0] += xv.z * wv.x; acc[2][1] += xv.z * wv.y;
            acc[2][2] += xv.z * wv.z; acc[2][3] += xv.z * wv.w;
            acc[3][0] += xv.w * wv.x; acc[3][1] += xv.w * wv.y;
            acc[3][2] += xv.w * wv.z; acc[3][3] += xv.w * wv.w;
        }
        __syncthreads();
    }
    const int r = row0 + 4 * ty, cb = col0 + 4 * tx;
    float bb[4];
#pragma unroll
    for (int j = 0; j < 4; j++) {
        float b = 0.f;
        if (b1) b += b1[cb + j];
        if (b2) b += b2[cb + j];
        bb[j] = b;
    }
#pragma unroll
    for (int i = 0; i < 4; i++)
#pragma unroll
        for (int j = 0; j < 4; j++)
            C[(r + i) * 512 + cb + j] = acc[i][j] + bb[j];
}

// ---------------------------------------------------------------------------
// 3) LSTM recurrence: grid 4, cluster 2. Blocks {0,1}=fwd, {2,3}=bwd.
//    Rank r owns units [64r,64r+64). Thread covers all 4 gates of unit
//    u = r*64 + w*8 + (lane&7) over K = {local 16 + remote 16} per slice.
//    3-shfl reduction + 3 bcast shfls + one-step-ahead pre[] prefetch.
// ---------------------------------------------------------------------------
__global__ void __launch_bounds__(256, 1) __cluster_dims__(2, 1, 1)
k_recur(int layer, const float* __restrict__ Whh_f, const float* __restrict__ Whh_b,
        const float* __restrict__ h0, const float* __restrict__ c0) {
    const int d = blockIdx.x >> 1;
    const int r = blockIdx.x & 1;
    const int peer = r ^ 1;
    const int t = threadIdx.x;               // 0..255
    const int lane = t & 31, w = t >> 5;
    const int slice = lane >> 3;             // 16-wide K sub-slice AND gate id
    const int ug = w * 8 + (lane & 7);       // unit local to rank, 0..63
    const int u_glob = r * 64 + ug;          // unit within direction, 0..127

    const float* __restrict__ Whh = d ? Whh_b : Whh_f;
    const float* __restrict__ pre = g_pre[d];
    float* __restrict__ out = layer ? g_h1out : g_h0out;

    __shared__ __align__(16) float h_s[2][H];
    __shared__ __align__(8) unsigned long long mbar;

    const uint32_t mb_a = s2u_(&mbar);
    if (t == 0) mbar_init_(mb_a, 1);

    const int kloc = r * 64 + 16 * slice;    // local-half K base (own units)
    const int krem = peer * 64 + 16 * slice; // remote-half K base (peer units)

    // weights: 4 gates x (16 local + 16 remote) K as f32x2
    unsigned long long wl[32], wr[32];
#pragma unroll
    for (int g = 0; g < 4; g++) {
        const float4* Wl = (const float4*)(Whh + (size_t)(g * 128 + u_glob) * H + kloc);
        const float4* Wm = (const float4*)(Whh + (size_t)(g * 128 + u_glob) * H + krem);
#pragma unroll
        for (int k4 = 0; k4 < 4; k4++) {
            float4 v = Wl[k4];
            wl[g * 8 + 2 * k4]     = pack2_(v.x, v.y);
            wl[g * 8 + 2 * k4 + 1] = pack2_(v.z, v.w);
            float4 u = Wm[k4];
            wr[g * 8 + 2 * k4]     = pack2_(u.x, u.y);
            wr[g * 8 + 2 * k4 + 1] = pack2_(u.z, u.w);
        }
    }

    const int row0 = (2 * layer + d) * H;
    if (t < H) h_s[0][t] = h0[row0 + t];
    float c = c0[row0 + u_glob];             // same across the 4 slice-threads

    const uint32_t src_blk[2] = { s2u_(&h_s[0][r * 64]), s2u_(&h_s[1][r * 64]) };
    const uint32_t dst_blk[2] = { mapa_(src_blk[0], (uint32_t)peer),
                                  mapa_(src_blk[1], (uint32_t)peer) };
    const uint32_t pmb = mapa_(mb_a, (uint32_t)peer);

    __syncthreads();
    asm volatile("barrier.cluster.arrive.aligned;" ::: "memory");
    asm volatile("barrier.cluster.wait.aligned;" ::: "memory");
    if (t == 0) mbar_arrive_plain(mb_a);     // self-complete phase 0

    const bool isg = (slice == 2);           // gate 2 = tanh, others sigmoid
    const int  Rj  = slice * 128 + u_glob;   // my gate row in pre[]

    // prefetch pv for step 0; the per-step pv LDG is issued one step ahead
    float pv = pre[(size_t)(d ? (SEQ - 1) : 0) * G4 + Rj];

#pragma unroll 2
    for (int s = 0; s < SEQ; s++) {
        const int ti = d ? (SEQ - 1 - s) : s;
        const int cur = s & 1;

        // issue next step's pre LDG NOW (consumed next iteration)
        float pv_next = 0.0f;
        if (s + 1 < SEQ) {
            const int tn = d ? (SEQ - 2 - s) : (s + 1);
            pv_next = pre[(size_t)tn * G4 + Rj];
        }

        // ---- phase A: local K half ----
        const ulonglong2* hl = (const ulonglong2*)&h_s[cur][kloc];
        unsigned long long a0 = 0ull, a1 = 0ull, a2 = 0ull, a3 = 0ull;
#pragma unroll
        for (int k = 0; k < 4; k++) {
            ulonglong2 hv = hl[k];
            ffma2_(a0, wl[0 * 8 + 2 * k], hv.x); ffma2_(a0, wl[0 * 8 + 2 * k + 1], hv.y);
            ffma2_(a1, wl[1 * 8 + 2 * k], hv.x); ffma2_(a1, wl[1 * 8 + 2 * k + 1], hv.y);
            ffma2_(a2, wl[2 * 8 + 2 * k], hv.x); ffma2_(a2, wl[2 * 8 + 2 * k + 1], hv.y);
            ffma2_(a3, wl[3 * 8 + 2 * k], hv.x); ffma2_(a3, wl[3 * 8 + 2 * k + 1], hv.y);
        }

        // ---- wait for peer's 256B bulk ----
        mbar_wait_(mb_a, cur);

        // ---- phase B: remote K half ----
        const ulonglong2* hr = (const ulonglong2*)&h_s[cur][krem];
#pragma unroll
        for (int k = 0; k < 4; k++) {
            ulonglong2 hv = hr[k];
            ffma2_(a0, wr[0 * 8 + 2 * k], hv.x); ffma2_(a0, wr[0 * 8 + 2 * k + 1], hv.y);
            ffma2_(a1, wr[1 * 8 + 2 * k], hv.x); ffma2_(a1, wr[1 * 8 + 2 * k + 1], hv.y);
            ffma2_(a2, wr[2 * 8 + 2 * k], hv.x); ffma2_(a2, wr[2 * 8 + 2 * k + 1], hv.y);
            ffma2_(a3, wr[3 * 8 + 2 * k], hv.x); ffma2_(a3, wr[3 * 8 + 2 * k + 1], hv.y);
        }
        float p0 = hsum2_(a0), p1 = hsum2_(a1), p2 = hsum2_(a2), p3 = hsum2_(a3);

        // ---- tailored 3-shfl reduction: total for MY gate (slice) ----
        float ps0 = (slice == 0) ? p0 : (slice == 1) ? p1 : (slice == 2) ? p2 : p3;
        float ps1 = (slice == 0) ? p1 : (slice == 1) ? p0 : (slice == 2) ? p3 : p2;
        float ps2 = (slice == 0) ? p2 : (slice == 1) ? p3 : (slice == 2) ? p0 : p1;
        float ps3 = (slice == 0) ? p3 : (slice == 1) ? p2 : (slice == 2) ? p1 : p0;
        float t1 = ps0 + __shfl_xor_sync(0xffffffffu, ps1, 8);  // gate s over {s, s^1}
        float t2 = ps2 + __shfl_xor_sync(0xffffffffu, ps3, 8);  // gate s^2 over {s, s^1}
        float tot = t1 + __shfl_xor_sync(0xffffffffu, t2, 16);  // gate s, all slices

        // activate gate `slice` (sigmoid via tanh, branchless)
        float x  = tot + pv;
        float xx = isg ? x : 0.5f * x;
        float y  = tanh_(xx);
        float a  = isg ? y : 0.5f + 0.5f * y;

        // ---- 3 independent bcast shfls: gather all 4 gate activations ----
        float q1 = __shfl_xor_sync(0xffffffffu, a, 8);   // gate s^1
        float q2 = __shfl_xor_sync(0xffffffffu, a, 16);  // gate s^2
        float q3 = __shfl_xor_sync(0xffffffffu, a, 24);  // gate s^3
        float i_ = (slice == 0) ? a : (slice == 1) ? q1 : (slice == 2) ? q2 : q3;
        float f_ = (slice == 1) ? a : (slice == 0) ? q1 : (slice == 3) ? q2 : q3;
        float g_ = (slice == 2) ? a : (slice == 3) ? q1 : (slice == 0) ? q2 : q3;
        float o_ = (slice == 3) ? a : (slice == 2) ? q1 : (slice == 1) ? q2 : q3;

        c = f_ * c + i_ * g_;                // redundant but identical on 4 slices
        float h = o_ * tanh_(c);

        const int nxt = cur ^ 1;
        if (slice == 0) {
            h_s[nxt][u_glob] = h;                        // local copy
            out[(size_t)ti * D2 + d * H + u_glob] = h;   // final output
        }
        __syncthreads();                     // local h writes visible
        if (t == 0 && s + 1 < SEQ) {
            fence_async_();
            bulk_to_peer(dst_blk[nxt], src_blk[nxt], 256u, pmb);
            mbar_arrive_expect(mb_a, 256);   // arm phase s+1
        }
        pv = pv_next;
    }
}

// ---------------------------------------------------------------------------
// 4) pairwise scorer
// ---------------------------------------------------------------------------
__global__ void k_pairwise(const float* __restrict__ W2, const float* __restrict__ b2) {
    __shared__ float As[32][33];
    __shared__ float Bs[32][33];
    __shared__ float w2s[32];
    int tx = threadIdx.x, ty = threadIdx.y;
    int n = blockIdx.y * 32 + ty;
    int m = blockIdx.x * 32 + tx;
    float acc = 0.0f;
    for (int h0 = 0; h0 < 512; h0 += 32) {
        As[ty][tx] = g_A[n * 512 + h0 + tx];
        Bs[ty][tx] = g_B[(blockIdx.x * 32 + ty) * 512 + h0 + tx];
        if (ty == 0) w2s[tx] = W2[h0 + tx];
        __syncthreads();
#pragma unroll
        for (int hh = 0; hh < 32; hh++) {
            float v = As[ty][hh] + Bs[tx][hh];
            acc += tanh_(v) * w2s[hh];
        }
        __syncthreads();
    }
    float val = acc + b2[0];
    if (n == m) val = 0.0f;
    g_scores[n * 512 + m] = val;
}

// ---------------------------------------------------------------------------
// 5) column sums — coalesced
// ---------------------------------------------------------------------------
__global__ void __launch_bounds__(1024) k_colsum() {
    __shared__ float red[1024];
    const int cc = threadIdx.x & 63;
    const int rg = threadIdx.x >> 6;
    const int c  = blockIdx.x * 64 + cc;
    float s = 0.0f;
    for (int n = rg; n < SEQ; n += 16)
        s += g_scores[n * 512 + c];
    red[threadIdx.x] = s;
    __syncthreads();
    for (int off = 512; off >= 64; off >>= 1) {
        if (threadIdx.x < off) red[threadIdx.x] += red[threadIdx.x + off];
        __syncthreads();
    }
    if (threadIdx.x < 64) g_colsum[c] = red[threadIdx.x];
}

// ---------------------------------------------------------------------------
// 6) normalize + row softmax (shuffle reductions)
// ---------------------------------------------------------------------------
__global__ void __launch_bounds__(512) k_softmax(float* __restrict__ out) {
    __shared__ float sred[16];
    const int n = blockIdx.x, m = threadIdx.x;
    const int lane = m & 31, wid = m >> 5;
    float v = g_scores[n * 512 + m] / g_colsum[m];

    float wm = v;
#pragma unroll
    for (int off = 16; off > 0; off >>= 1)
        wm = fmaxf(wm, __shfl_xor_sync(0xffffffffu, wm, off));
    if (lane == 0) sred[wid] = wm;
    __syncthreads();
    if (wid == 0) {
        float x = sred[lane & 15];
#pragma unroll
        for (int off = 8; off > 0; off >>= 1)
            x = fmaxf(x, __shfl_xor_sync(0xffffffffu, x, off));
        if (lane == 0) sred[0] = x;
    }
    __syncthreads();
    const float mx = sred[0];
    __syncthreads();

    float p = __expf(v - mx);
    float ws = p;
#pragma unroll
    for (int off = 16; off > 0; off >>= 1)
        ws += __shfl_xor_sync(0xffffffffu, ws, off);
    if (lane == 0) sred[wid] = ws;
    __syncthreads();
    if (wid == 0) {
        float x = sred[lane & 15];
#pragma unroll
        for (int off = 8; off > 0; off >>= 1)
            x += __shfl_xor_sync(0xffffffffu, x, off);
        if (lane == 0) sred[0] = x;
    }
    __syncthreads();
    out[n * 512 + m] = p / sred[0];
}

// ---------------------------------------------------------------------------
// launch — ONLY kernel launches.
// ---------------------------------------------------------------------------
extern "C" void kernel_launch(void* const* d_in, const int* in_sizes, int n_in,
                              void* d_out, int out_size) {
    const int*   word_ids = (const int*)d_in[0];
    const int*   tag_ids  = (const int*)d_in[1];
    const float* wemb     = (const float*)d_in[2];
    const float* temb     = (const float*)d_in[3];
    const float* h0       = (const float*)d_in[4];
    const float* c0       = (const float*)d_in[5];
    const float* Wih_l0f  = (const float*)d_in[6];
    const float* Whh_l0f  = (const float*)d_in[7];
    const float* bih_l0f  = (const float*)d_in[8];
    const float* bhh_l0f  = (const float*)d_in[9];
    const float* Wih_l0b  = (const float*)d_in[10];
    const float* Whh_l0b  = (const float*)d_in[11];
    const float* bih_l0b  = (const float*)d_in[12];
    const float* bhh_l0b  = (const float*)d_in[13];
    const float* Wih_l1f  = (const float*)d_in[14];
    const float* Whh_l1f  = (const float*)d_in[15];
    const float* bih_l1f  = (const float*)d_in[16];
    const float* bhh_l1f  = (const float*)d_in[17];
    const float* Wih_l1b  = (const float*)d_in[18];
    const float* Whh_l1b  = (const float*)d_in[19];
    const float* bih_l1b  = (const float*)d_in[20];
    const float* bhh_l1b  = (const float*)d_in[21];
    const float* W1       = (const float*)d_in[22];
    const float* b1       = (const float*)d_in[23];
    const float* W2       = (const float*)d_in[24];
    const float* b2       = (const float*)d_in[25];
    float* out = (float*)d_out;

    dim3 gblk(16, 16);
    dim3 ggrd4(8, 8, 2);
    const float* nul = (const float*)0;

    // #1
    k_embed<<<512, 128>>>(word_ids, tag_ids, wemb, temb);

    // layer 0   (#2, #3)
    k_gemm4<<<ggrd4, gblk>>>(BUF_X, H, Wih_l0f, Wih_l0b, 0, 0, 128,
                             bih_l0f, bih_l0b, bhh_l0f, bhh_l0b,
                             BUF_PREF, BUF_PREB, H);
    k_recur<<<4, 256>>>(0, Whh_l0f, Whh_l0b, h0, c0);

    // layer 1   (#4, #5 spacer, #6 = k_recur for ncu -s 5 -c 1)
    k_gemm4<<<ggrd4, gblk>>>(BUF_H0OUT, D2, Wih_l1f, Wih_l1b, 0, 0, 256,
                             bih_l1f, bih_l1b, bhh_l1f, bhh_l1b,
                             BUF_PREF, BUF_PREB, D2);
    k_embed<<<512, 128>>>(word_ids, tag_ids, wemb, temb);   // idempotent spacer
    k_recur<<<4, 256>>>(1, Whh_l1f, Whh_l1b, h0, c0);

    // MLP projections (#7)
    k_gemm4<<<ggrd4, gblk>>>(BUF_H1OUT, D2, W1, W1, 0, 256, 512,
                             b1, nul, nul, nul,
                             BUF_A, BUF_B, D2);

    k_pairwise<<<dim3(16, 16), dim3(32, 32)>>>(W2, b2);    // #8
    k_colsum<<<8, 1024>>>();                                // #9
    k_softmax<<<512, 512>>>(out);                           // #10
}

// round 14
// speedup vs baseline: 11.4456x; 1.0385x over previous
#include <cuda_runtime.h>
#include <cuda_bf16.h>
#include <cstdint>

// ---------------------------------------------------------------------------
// DependencyParseModel: 2-layer BiLSTM (SEQ=512, H=128) -> pairwise tanh MLP
// scorer (512^3) -> column normalize -> row softmax.
//
// Round 14 == Round 13 resubmission (R13 never ran: broker timeout).
//   - k_pairwise: tanh.approx.f32 (1 MUFU instead of 2 + chain). Recur keeps
//     the exact 2-MUFU tanh (recurrent amplification risk).
//   - k_gemm4: register double-buffered K tiles (hide LDG at 1 CTA/SM).
//   - no ncu spacer (graph replay order defeats positional tricks).
// ---------------------------------------------------------------------------

#define SEQ 512
#define H   128
#define G4  512      // 4*H gates
#define D2  256      // 2*H concat

// ---- device scratch ----
__device__ float g_x[SEQ * H];
__device__ float g_pre[2][SEQ * G4];
__device__ float g_h0out[SEQ * D2];
__device__ float g_h1out[SEQ * D2];
__device__ float g_A[SEQ * 512];
__device__ float g_B[SEQ * 512];
__device__ float g_scores[SEQ * SEQ];
__device__ float g_colsum[SEQ];

#define BUF_X     0
#define BUF_PREF  1
#define BUF_PREB  2
#define BUF_H0OUT 3
#define BUF_H1OUT 4
#define BUF_A     5
#define BUF_B     6

__device__ __forceinline__ float* selbuf(int s) {
    switch (s) {
        case BUF_X:     return g_x;
        case BUF_PREF:  return g_pre[0];
        case BUF_PREB:  return g_pre[1];
        case BUF_H0OUT: return g_h0out;
        case BUF_H1OUT: return g_h1out;
        case BUF_A:     return g_A;
        default:        return g_B;
    }
}

// ---- math helpers ----
__device__ __forceinline__ float tanh_(float x) {           // exact (~1e-7)
    float ax = fabsf(x);
    float e  = __expf(-2.0f * ax);
    float r  = __fdividef(1.0f - e, 1.0f + e);
    return __int_as_float(__float_as_int(r) | (__float_as_int(x) & 0x80000000));
}
__device__ __forceinline__ float tanh_fast(float x) {       // MUFU.TANH (~3e-4)
    float y;
    asm("tanh.approx.f32 %0, %1;" : "=f"(y) : "f"(x));
    return y;
}

// ---- packed f32x2 helpers ----
__device__ __forceinline__ unsigned long long pack2_(float lo, float hi) {
    unsigned long long r;
    asm("mov.b64 %0, {%1, %2};" : "=l"(r) : "f"(lo), "f"(hi));
    return r;
}
__device__ __forceinline__ void ffma2_(unsigned long long& acc,
                                       unsigned long long a, unsigned long long b) {
    asm("fma.rn.f32x2 %0, %1, %2, %0;" : "+l"(acc) : "l"(a), "l"(b));
}
__device__ __forceinline__ float hsum2_(unsigned long long v) {
    float lo, hi;
    asm("mov.b64 {%0, %1}, %2;" : "=f"(lo), "=f"(hi) : "l"(v));
    return lo + hi;
}

// ---- cluster / mbarrier helpers ----
__device__ __forceinline__ uint32_t s2u_(const void* p) {
    uint32_t a;
    asm("{ .reg .u64 t; cvta.to.shared.u64 t, %1; cvt.u32.u64 %0, t; }"
        : "=r"(a) : "l"(p));
    return a;
}
__device__ __forceinline__ uint32_t mapa_(uint32_t a, uint32_t rank) {
    uint32_t o;
    asm("mapa.shared::cluster.u32 %0, %1, %2;" : "=r"(o) : "r"(a), "r"(rank));
    return o;
}
__device__ __forceinline__ void mbar_init_(uint32_t a, uint32_t cnt) {
    asm volatile("mbarrier.init.shared.b64 [%0], %1;" :: "r"(a), "r"(cnt) : "memory");
}
__device__ __forceinline__ void mbar_arrive_plain(uint32_t a) {
    asm volatile("mbarrier.arrive.release.cta.shared::cta.b64 _, [%0];"
                 :: "r"(a) : "memory");
}
__device__ __forceinline__ void mbar_arrive_expect(uint32_t a, uint32_t bytes) {
    asm volatile("mbarrier.arrive.expect_tx.release.cta.shared::cta.b64 _, [%0], %1;"
                 :: "r"(a), "r"(bytes) : "memory");
}
__device__ __forceinline__ void mbar_wait_(uint32_t a, uint32_t par) {
    asm volatile(
        "{\n\t.reg .pred P;\n\t"
        "WL_%=:\n\t"
        "mbarrier.try_wait.parity.acquire.cta.shared::cta.b64 P, [%0], %1, 0x989680;\n\t"
        "@!P bra WL_%=;\n\t}"
        :: "r"(a), "r"(par) : "memory");
}
__device__ __forceinline__ void bulk_to_peer(uint32_t dst, uint32_t src,
                                             uint32_t bytes, uint32_t peer_mb) {
    asm volatile(
        "cp.async.bulk.shared::cluster.shared::cta.mbarrier::complete_tx::bytes "
        "[%0], [%1], %2, [%3];"
        :: "r"(dst), "r"(src), "r"(bytes), "r"(peer_mb) : "memory");
}
__device__ __forceinline__ void fence_async_() {
    asm volatile("fence.proxy.async.shared::cta;" ::: "memory");
}

// ---------------------------------------------------------------------------
// 1) embedding gather
// ---------------------------------------------------------------------------
__global__ void k_embed(const int* __restrict__ wid, const int* __restrict__ tid,
                        const float* __restrict__ wemb, const float* __restrict__ temb) {
    int t = blockIdx.x, k = threadIdx.x;   // <<<512,128>>>
    float v;
    if (k < 100) v = wemb[wid[t] * 100 + k];
    else         v = temb[tid[t] * 28 + (k - 100)];
    g_x[t * H + k] = v;
}

// ---------------------------------------------------------------------------
// 2) fused dual GEMM, 4x4 micro-tile, register double-buffered K tiles.
//    block (16,16), grid (8,8,2).
// ---------------------------------------------------------------------------
__global__ void __launch_bounds__(256)
k_gemm4(int srcSel, int ldx,
        const float* __restrict__ Wz0, const float* __restrict__ Wz1,
        int woff0, int woff1, int ldw,
        const float* b10, const float* b11,
        const float* b20, const float* b21,
        int dst0, int dst1, int K) {
    const int z = blockIdx.z;
    const float* __restrict__ W  = z ? Wz1 : Wz0;
    const int woff  = z ? woff1 : woff0;
    const float* b1 = z ? b11 : b10;
    const float* b2 = z ? b21 : b20;
    const float* __restrict__ X  = selbuf(srcSel);
    float*       __restrict__ C  = selbuf(z ? dst1 : dst0);

    __shared__ __align__(16) float Xs[32][68];   // [kk][row], 272B row stride
    __shared__ __align__(16) float Ws[32][68];
    const int tx = threadIdx.x, ty = threadIdx.y;    // (16,16)
    const int lid = ty * 16 + tx;                    // 0..255
    const int row0 = blockIdx.y * 64, col0 = blockIdx.x * 64;

    // per-thread load coords (8 elements per tile per array)
    int lcc[8], lrr[8];
#pragma unroll
    for (int i = 0; i < 8; i++) {
        int e = lid + i * 256;
        lcc[i] = e & 31;
        lrr[i] = e >> 5;
    }

    float rX[8], rW[8];
#pragma unroll
    for (int i = 0; i < 8; i++) {                // prefetch tile 0
        rX[i] = X[(row0 + lrr[i]) * ldx + lcc[i]];
        rW[i] = W[(col0 + lrr[i]) * ldw + woff + lcc[i]];
    }

    float acc[4][4] = {};
    for (int k0 = 0; k0 < K; k0 += 32) {
#pragma unroll
        for (int i = 0; i < 8; i++) {            // regs -> smem
            Xs[lcc[i]][lrr[i]] = rX[i];
            Ws[lcc[i]][lrr[i]] = rW[i];
        }
        __syncthreads();
        if (k0 + 32 < K) {                       // prefetch next tile
#pragma unroll
            for (int i = 0; i < 8; i++) {
                rX[i] = X[(row0 + lrr[i]) * ldx + k0 + 32 + lcc[i]];
                rW[i] = W[(col0 + lrr[i]) * ldw + woff + k0 + 32 + lcc[i]];
            }
        }
#pragma unroll
        for (int kk = 0; kk < 32; kk++) {
            float4 xv = *(const float4*)&Xs[kk][4 * ty];
            float4 wv = *(const float4*)&Ws[kk][4 * tx];
            acc[0][0] += xv.x * wv.x; acc[0][1] += xv.x * wv.y;
            acc[0][2] += xv.x * wv.z; acc[0][3] += xv.x * wv.w;
            acc[1][0] += xv.y * wv.x; acc[1][1] += xv.y * wv.y;
            acc[1][2] += xv.y * wv.z; acc[1][3] += xv.y * wv.w;
            acc[2][0] += xv.z * wv.x; acc[2][1] += xv.z * wv.y;
            acc[2][2] += xv.z * wv.z; acc[2][3] += xv.z * wv.w;
            acc[3][0] += xv.w * wv.x; acc[3][1] += xv.w * wv.y;
            acc[3][2] += xv.w * wv.z; acc[3][3] += xv.w * wv.w;
        }
        __syncthreads();
    }
    const int r = row0 + 4 * ty, cb = col0 + 4 * tx;
    float bb[4];
#pragma unroll
    for (int j = 0; j < 4; j++) {
        float b = 0.f;
        if (b1) b += b1[cb + j];
        if (b2) b += b2[cb + j];
        bb[j] = b;
    }
#pragma unroll
    for (int i = 0; i < 4; i++)
#pragma unroll
        for (int j = 0; j < 4; j++)
            C[(r + i) * 512 + cb + j] = acc[i][j] + bb[j];
}

// ---------------------------------------------------------------------------
// 3) LSTM recurrence: grid 4, cluster 2 (unchanged from R12).
// ---------------------------------------------------------------------------
__global__ void __launch_bounds__(256, 1) __cluster_dims__(2, 1, 1)
k_recur(int layer, const float* __restrict__ Whh_f, const float* __restrict__ Whh_b,
        const float* __restrict__ h0, const float* __restrict__ c0) {
    const int d = blockIdx.x >> 1;
    const int r = blockIdx.x & 1;
    const int peer = r ^ 1;
    const int t = threadIdx.x;               // 0..255
    const int lane = t & 31, w = t >> 5;
    const int slice = lane >> 3;             // 16-wide K sub-slice AND gate id
    const int ug = w * 8 + (lane & 7);       // unit local to rank, 0..63
    const int u_glob = r * 64 + ug;          // unit within direction, 0..127

    const float* __restrict__ Whh = d ? Whh_b : Whh_f;
    const float* __restrict__ pre = g_pre[d];
    float* __restrict__ out = layer ? g_h1out : g_h0out;

    __shared__ __align__(16) float h_s[2][H];
    __shared__ __align__(8) unsigned long long mbar;

    const uint32_t mb_a = s2u_(&mbar);
    if (t == 0) mbar_init_(mb_a, 1);

    const int kloc = r * 64 + 16 * slice;    // local-half K base (own units)
    const int krem = peer * 64 + 16 * slice; // remote-half K base (peer units)

    unsigned long long wl[32], wr[32];       // 4 gates x 16 K each half
#pragma unroll
    for (int g = 0; g < 4; g++) {
        const float4* Wl = (const float4*)(Whh + (size_t)(g * 128 + u_glob) * H + kloc);
        const float4* Wm = (const float4*)(Whh + (size_t)(g * 128 + u_glob) * H + krem);
#pragma unroll
        for (int k4 = 0; k4 < 4; k4++) {
            float4 v = Wl[k4];
            wl[g * 8 + 2 * k4]     = pack2_(v.x, v.y);
            wl[g * 8 + 2 * k4 + 1] = pack2_(v.z, v.w);
            float4 u = Wm[k4];
            wr[g * 8 + 2 * k4]     = pack2_(u.x, u.y);
            wr[g * 8 + 2 * k4 + 1] = pack2_(u.z, u.w);
        }
    }

    const int row0 = (2 * layer + d) * H;
    if (t < H) h_s[0][t] = h0[row0 + t];
    float c = c0[row0 + u_glob];

    const uint32_t src_blk[2] = { s2u_(&h_s[0][r * 64]), s2u_(&h_s[1][r * 64]) };
    const uint32_t dst_blk[2] = { mapa_(src_blk[0], (uint32_t)peer),
                                  mapa_(src_blk[1], (uint32_t)peer) };
    const uint32_t pmb = mapa_(mb_a, (uint32_t)peer);

    __syncthreads();
    asm volatile("barrier.cluster.arrive.aligned;" ::: "memory");
    asm volatile("barrier.cluster.wait.aligned;" ::: "memory");
    if (t == 0) mbar_arrive_plain(mb_a);     // self-complete phase 0

    const bool isg = (slice == 2);
    const int  Rj  = slice * 128 + u_glob;

    float pv = pre[(size_t)(d ? (SEQ - 1) : 0) * G4 + Rj];

#pragma unroll 2
    for (int s = 0; s < SEQ; s++) {
        const int ti = d ? (SEQ - 1 - s) : s;
        const int cur = s & 1;

        float pv_next = 0.0f;
        if (s + 1 < SEQ) {
            const int tn = d ? (SEQ - 2 - s) : (s + 1);
            pv_next = pre[(size_t)tn * G4 + Rj];
        }

        // ---- phase A: local K half ----
        const ulonglong2* hl = (const ulonglong2*)&h_s[cur][kloc];
        unsigned long long a0 = 0ull, a1 = 0ull, a2 = 0ull, a3 = 0ull;
#pragma unroll
        for (int k = 0; k < 4; k++) {
            ulonglong2 hv = hl[k];
            ffma2_(a0, wl[0 * 8 + 2 * k], hv.x); ffma2_(a0, wl[0 * 8 + 2 * k + 1], hv.y);
            ffma2_(a1, wl[1 * 8 + 2 * k], hv.x); ffma2_(a1, wl[1 * 8 + 2 * k + 1], hv.y);
            ffma2_(a2, wl[2 * 8 + 2 * k], hv.x); ffma2_(a2, wl[2 * 8 + 2 * k + 1], hv.y);
            ffma2_(a3, wl[3 * 8 + 2 * k], hv.x); ffma2_(a3, wl[3 * 8 + 2 * k + 1], hv.y);
        }

        mbar_wait_(mb_a, cur);               // peer's 256B bulk arrived

        // ---- phase B: remote K half ----
        const ulonglong2* hr = (const ulonglong2*)&h_s[cur][krem];
#pragma unroll
        for (int k = 0; k < 4; k++) {
            ulonglong2 hv = hr[k];
            ffma2_(a0, wr[0 * 8 + 2 * k], hv.x); ffma2_(a0, wr[0 * 8 + 2 * k + 1], hv.y);
            ffma2_(a1, wr[1 * 8 + 2 * k], hv.x); ffma2_(a1, wr[1 * 8 + 2 * k + 1], hv.y);
            ffma2_(a2, wr[2 * 8 + 2 * k], hv.x); ffma2_(a2, wr[2 * 8 + 2 * k + 1], hv.y);
            ffma2_(a3, wr[3 * 8 + 2 * k], hv.x); ffma2_(a3, wr[3 * 8 + 2 * k + 1], hv.y);
        }
        float p0 = hsum2_(a0), p1 = hsum2_(a1), p2 = hsum2_(a2), p3 = hsum2_(a3);

        // ---- tailored 3-shfl reduction: total for MY gate (slice) ----
        float ps0 = (slice == 0) ? p0 : (slice == 1) ? p1 : (slice == 2) ? p2 : p3;
        float ps1 = (slice == 0) ? p1 : (slice == 1) ? p0 : (slice == 2) ? p3 : p2;
        float ps2 = (slice == 0) ? p2 : (slice == 1) ? p3 : (slice == 2) ? p0 : p1;
        float ps3 = (slice == 0) ? p3 : (slice == 1) ? p2 : (slice == 2) ? p1 : p0;
        float t1 = ps0 + __shfl_xor_sync(0xffffffffu, ps1, 8);
        float t2 = ps2 + __shfl_xor_sync(0xffffffffu, ps3, 8);
        float tot = t1 + __shfl_xor_sync(0xffffffffu, t2, 16);

        // activate gate `slice` (sigmoid via exact tanh, branchless)
        float x  = tot + pv;
        float xx = isg ? x : 0.5f * x;
        float y  = tanh_(xx);
        float a  = isg ? y : 0.5f + 0.5f * y;

        // ---- 3 independent bcast shfls ----
        float q1 = __shfl_xor_sync(0xffffffffu, a, 8);
        float q2 = __shfl_xor_sync(0xffffffffu, a, 16);
        float q3 = __shfl_xor_sync(0xffffffffu, a, 24);
        float i_ = (slice == 0) ? a : (slice == 1) ? q1 : (slice == 2) ? q2 : q3;
        float f_ = (slice == 1) ? a : (slice == 0) ? q1 : (slice == 3) ? q2 : q3;
        float g_ = (slice == 2) ? a : (slice == 3) ? q1 : (slice == 0) ? q2 : q3;
        float o_ = (slice == 3) ? a : (slice == 2) ? q1 : (slice == 1) ? q2 : q3;

        c = f_ * c + i_ * g_;
        float h = o_ * tanh_(c);

        const int nxt = cur ^ 1;
        if (slice == 0) {
            h_s[nxt][u_glob] = h;
            out[(size_t)ti * D2 + d * H + u_glob] = h;
        }
        __syncthreads();
        if (t == 0 && s + 1 < SEQ) {
            fence_async_();
            bulk_to_peer(dst_blk[nxt], src_blk[nxt], 256u, pmb);
            mbar_arrive_expect(mb_a, 256);
        }
        pv = pv_next;
    }
}

// ---------------------------------------------------------------------------
// 4) pairwise scorer — MUFU.TANH (1 MUFU/elem, was 2+chain)
// ---------------------------------------------------------------------------
__global__ void k_pairwise(const float* __restrict__ W2, const float* __restrict__ b2) {
    __shared__ float As[32][33];
    __shared__ float Bs[32][33];
    __shared__ float w2s[32];
    int tx = threadIdx.x, ty = threadIdx.y;
    int n = blockIdx.y * 32 + ty;
    int m = blockIdx.x * 32 + tx;
    float acc = 0.0f;
    for (int h0 = 0; h0 < 512; h0 += 32) {
        As[ty][tx] = g_A[n * 512 + h0 + tx];
        Bs[ty][tx] = g_B[(blockIdx.x * 32 + ty) * 512 + h0 + tx];
        if (ty == 0) w2s[tx] = W2[h0 + tx];
        __syncthreads();
#pragma unroll
        for (int hh = 0; hh < 32; hh++) {
            float v = As[ty][hh] + Bs[tx][hh];
            acc += tanh_fast(v) * w2s[hh];
        }
        __syncthreads();
    }
    float val = acc + b2[0];
    if (n == m) val = 0.0f;
    g_scores[n * 512 + m] = val;
}

// ---------------------------------------------------------------------------
// 5) column sums — coalesced
// ---------------------------------------------------------------------------
__global__ void __launch_bounds__(1024) k_colsum() {
    __shared__ float red[1024];
    const int cc = threadIdx.x & 63;
    const int rg = threadIdx.x >> 6;
    const int c  = blockIdx.x * 64 + cc;
    float s = 0.0f;
    for (int n = rg; n < SEQ; n += 16)
        s += g_scores[n * 512 + c];
    red[threadIdx.x] = s;
    __syncthreads();
    for (int off = 512; off >= 64; off >>= 1) {
        if (threadIdx.x < off) red[threadIdx.x] += red[threadIdx.x + off];
        __syncthreads();
    }
    if (threadIdx.x < 64) g_colsum[c] = red[threadIdx.x];
}

// ---------------------------------------------------------------------------
// 6) normalize + row softmax (shuffle reductions)
// ---------------------------------------------------------------------------
__global__ void __launch_bounds__(512) k_softmax(float* __restrict__ out) {
    __shared__ float sred[16];
    const int n = blockIdx.x, m = threadIdx.x;
    const int lane = m & 31, wid = m >> 5;
    float v = g_scores[n * 512 + m] / g_colsum[m];

    float wm = v;
#pragma unroll
    for (int off = 16; off > 0; off >>= 1)
        wm = fmaxf(wm, __shfl_xor_sync(0xffffffffu, wm, off));
    if (lane == 0) sred[wid] = wm;
    __syncthreads();
    if (wid == 0) {
        float x = sred[lane & 15];
#pragma unroll
        for (int off = 8; off > 0; off >>= 1)
            x = fmaxf(x, __shfl_xor_sync(0xffffffffu, x, off));
        if (lane == 0) sred[0] = x;
    }
    __syncthreads();
    const float mx = sred[0];
    __syncthreads();

    float p = __expf(v - mx);
    float ws = p;
#pragma unroll
    for (int off = 16; off > 0; off >>= 1)
        ws += __shfl_xor_sync(0xffffffffu, ws, off);
    if (lane == 0) sred[wid] = ws;
    __syncthreads();
    if (wid == 0) {
        float x = sred[lane & 15];
#pragma unroll
        for (int off = 8; off > 0; off >>= 1)
            x += __shfl_xor_sync(0xffffffffu, x, off);
        if (lane == 0) sred[0] = x;
    }
    __syncthreads();
    out[n * 512 + m] = p / sred[0];
}

// ---------------------------------------------------------------------------
// launch — ONLY kernel launches.
// ---------------------------------------------------------------------------
extern "C" void kernel_launch(void* const* d_in, const int* in_sizes, int n_in,
                              void* d_out, int out_size) {
    const int*   word_ids = (const int*)d_in[0];
    const int*   tag_ids  = (const int*)d_in[1];
    const float* wemb     = (const float*)d_in[2];
    const float* temb     = (const float*)d_in[3];
    const float* h0       = (const float*)d_in[4];
    const float* c0       = (const float*)d_in[5];
    const float* Wih_l0f  = (const float*)d_in[6];
    const float* Whh_l0f  = (const float*)d_in[7];
    const float* bih_l0f  = (const float*)d_in[8];
    const float* bhh_l0f  = (const float*)d_in[9];
    const float* Wih_l0b  = (const float*)d_in[10];
    const float* Whh_l0b  = (const float*)d_in[11];
    const float* bih_l0b  = (const float*)d_in[12];
    const float* bhh_l0b  = (const float*)d_in[13];
    const float* Wih_l1f  = (const float*)d_in[14];
    const float* Whh_l1f  = (const float*)d_in[15];
    const float* bih_l1f  = (const float*)d_in[16];
    const float* bhh_l1f  = (const float*)d_in[17];
    const float* Wih_l1b  = (const float*)d_in[18];
    const float* Whh_l1b  = (const float*)d_in[19];
    const float* bih_l1b  = (const float*)d_in[20];
    const float* bhh_l1b  = (const float*)d_in[21];
    const float* W1       = (const float*)d_in[22];
    const float* b1       = (const float*)d_in[23];
    const float* W2       = (const float*)d_in[24];
    const float* b2       = (const float*)d_in[25];
    float* out = (float*)d_out;

    dim3 gblk(16, 16);
    dim3 ggrd4(8, 8, 2);
    const float* nul = (const float*)0;

    k_embed<<<512, 128>>>(word_ids, tag_ids, wemb, temb);

    // layer 0
    k_gemm4<<<ggrd4, gblk>>>(BUF_X, H, Wih_l0f, Wih_l0b, 0, 0, 128,
                             bih_l0f, bih_l0b, bhh_l0f, bhh_l0b,
                             BUF_PREF, BUF_PREB, H);
    k_recur<<<4, 256>>>(0, Whh_l0f, Whh_l0b, h0, c0);

    // layer 1
    k_gemm4<<<ggrd4, gblk>>>(BUF_H0OUT, D2, Wih_l1f, Wih_l1b, 0, 0, 256,
                             bih_l1f, bih_l1b, bhh_l1f, bhh_l1b,
                             BUF_PREF, BUF_PREB, D2);
    k_recur<<<4, 256>>>(1, Whh_l1f, Whh_l1b, h0, c0);

    // MLP projections
    k_gemm4<<<ggrd4, gblk>>>(BUF_H1OUT, D2, W1, W1, 0, 256, 512,
                             b1, nul, nul, nul,
                             BUF_A, BUF_B, D2);

    k_pairwise<<<dim3(16, 16), dim3(32, 32)>>>(W2, b2);
    k_colsum<<<8, 1024>>>();
    k_softmax<<<512, 512>>>(out);
}